// round 12
// baseline (speedup 1.0000x reference)
#include <cuda_runtime.h>

#define H     128
#define NT    256
#define NMAX  10016
#define E1MAX 80000
#define E2MAX 80000
#define WCAP  (E1MAX*16)

// ------- scratch (static device globals; no runtime allocation) ----------
__device__ int   g_ptr[NMAX + 2];
__device__ int   g_cnt[E2MAX];
__device__ int   g_part[128];
__device__ int   g_wptr[E2MAX + 1];
__device__ int   g_weik[WCAP];
__device__ int   g_wekj[WCAP];
__device__ float g_U[(size_t)E1MAX * H];
__device__ float g_V[(size_t)E1MAX * H];
__device__ float g_Z[(size_t)E2MAX * H];

// ------------------------- helpers ---------------------------------------
__device__ __forceinline__ float to_tf32(float x) {
    unsigned u;
    asm("cvt.rna.tf32.f32 %0, %1;" : "=r"(u) : "f"(x));
    return __uint_as_float(u);
}

__device__ __forceinline__ void mma_tf32(float c[4], const unsigned a[4],
                                         unsigned b0, unsigned b1) {
    asm volatile(
        "mma.sync.aligned.m16n8k8.row.col.f32.tf32.tf32.f32 "
        "{%0,%1,%2,%3}, {%4,%5,%6,%7}, {%8,%9}, {%0,%1,%2,%3};"
        : "+f"(c[0]), "+f"(c[1]), "+f"(c[2]), "+f"(c[3])
        : "r"(a[0]), "r"(a[1]), "r"(a[2]), "r"(a[3]), "r"(b0), "r"(b1));
}

__device__ __forceinline__ void cpa16(void* sdst, const void* gsrc) {
    unsigned s = (unsigned)__cvta_generic_to_shared(sdst);
    asm volatile("cp.async.cg.shared.global [%0], [%1], 16;\n" :: "r"(s), "l"(gsrc));
}
#define CP_COMMIT() asm volatile("cp.async.commit_group;\n")
#define CP_WAIT0()  asm volatile("cp.async.wait_group 0;\n")
#define CP_WAIT1()  asm volatile("cp.async.wait_group 1;\n")

// ---------------- CSR ptr: g_ptr[v] = lower_bound(src1, v) ---------------
__global__ void k_ptr(const int* __restrict__ src1, int E1, const int* __restrict__ nn_p) {
    int v = blockIdx.x * blockDim.x + threadIdx.x;
    int nn = *nn_p;
    if (v > nn || v > NMAX) return;
    int lo = 0, hi = E1;
    while (lo < hi) { int mid = (lo + hi) >> 1; if (src1[mid] < v) lo = mid + 1; else hi = mid; }
    g_ptr[v] = lo;
}

// ------------- per-e2-edge wedge count (sorted-by-eij build) --------------
__global__ void k_count(const int* __restrict__ src2, const int* __restrict__ dst2,
                        const int* __restrict__ dst1, int E2) {
    int q = blockIdx.x * blockDim.x + threadIdx.x;
    if (q >= E2) return;
    int i = src2[q], j = dst2[q];
    int c = 0;
    if (i != j) {
        int b0 = g_ptr[i], e0 = g_ptr[i + 1];
        for (int t = b0; t < e0; t++) {
            int k = dst1[t];
            if (k == i || k == j) continue;
            int b1 = g_ptr[k], e1 = g_ptr[k + 1];
            for (int u = b1; u < e1; u++)
                if (dst1[u] == j) c++;
        }
    }
    g_cnt[q] = c;
}

// ----------------------- 3-phase exclusive scan ---------------------------
__global__ void k_scan_part(int n) {
    int blk = blockIdx.x, tid = threadIdx.x, lane = tid & 31, wid = tid >> 5;
    int base = blk * 2048 + tid * 8;
    int s = 0;
#pragma unroll
    for (int i = 0; i < 8; i++) { int idx = base + i; if (idx < n) s += g_cnt[idx]; }
#pragma unroll
    for (int off = 16; off > 0; off >>= 1) s += __shfl_down_sync(0xffffffffu, s, off);
    __shared__ int red[8];
    if (lane == 0) red[wid] = s;
    __syncthreads();
    if (tid == 0) {
        int tot = 0;
#pragma unroll
        for (int w = 0; w < 8; w++) tot += red[w];
        g_part[blk] = tot;
    }
}
__global__ void k_scan_top(int nb, int n) {
    if (threadIdx.x == 0) {
        int acc = 0;
        for (int b = 0; b < nb; b++) { int v = g_part[b]; g_part[b] = acc; acc += v; }
        g_wptr[n] = acc;
    }
}
__global__ void k_scan_write(int n) {
    int blk = blockIdx.x, tid = threadIdx.x, lane = tid & 31, wid = tid >> 5;
    int base = blk * 2048 + tid * 8;
    int v[8]; int s = 0;
#pragma unroll
    for (int i = 0; i < 8; i++) {
        int idx = base + i;
        v[i] = (idx < n) ? g_cnt[idx] : 0;
        s += v[i];
    }
    int x = s;
#pragma unroll
    for (int off = 1; off < 32; off <<= 1) {
        int t = __shfl_up_sync(0xffffffffu, x, off);
        if (lane >= off) x += t;
    }
    __shared__ int wsum[8];
    if (lane == 31) wsum[wid] = x;
    __syncthreads();
    __shared__ int wexc[8];
    if (tid == 0) {
        int acc = 0;
#pragma unroll
        for (int w = 0; w < 8; w++) { wexc[w] = acc; acc += wsum[w]; }
    }
    __syncthreads();
    int run = g_part[blk] + wexc[wid] + x - s;
#pragma unroll
    for (int i = 0; i < 8; i++) {
        int idx = base + i;
        if (idx < n) g_wptr[idx] = run;
        run += v[i];
    }
}

__global__ void k_fill(const int* __restrict__ src2, const int* __restrict__ dst2,
                       const int* __restrict__ dst1, int E2) {
    int q = blockIdx.x * blockDim.x + threadIdx.x;
    if (q >= E2) return;
    int i = src2[q], j = dst2[q];
    if (i == j) return;
    int pos = g_wptr[q];
    int b0 = g_ptr[i], e0 = g_ptr[i + 1];
    for (int t = b0; t < e0; t++) {
        int k = dst1[t];
        if (k == i || k == j) continue;
        int b1 = g_ptr[k], e1 = g_ptr[k + 1];
        for (int u = b1; u < e1; u++)
            if (dst1[u] == j) {
                if (pos < WCAP) { g_weik[pos] = t; g_wekj[pos] = u; }
                pos++;
            }
    }
}

// ---------- merged U+V projection (M=64, occ 2, cp.async pipelined) -------
__global__ void __launch_bounds__(256, 2) k_projUV(
    const float* __restrict__ t_e2, const float* __restrict__ h,
    const int* __restrict__ e1e2, const int* __restrict__ src1,
    const int* __restrict__ dst1, const float* __restrict__ rbf1,
    int E1, const float* __restrict__ W,
    float* __restrict__ outU, float* __restrict__ outV) {
    extern __shared__ float sm[];
    float(*As)[64][36]  = (float(*)[64][36])sm;                    // 2 stages
    float(*BU)[32][132] = (float(*)[32][132])(sm + 2 * 64 * 36);
    float(*BV)[32][132] = (float(*)[32][132])(sm + 2 * 64 * 36 + 2 * 32 * 132);
    int* s_row = (int*)(sm + 2 * 64 * 36 + 4 * 32 * 132);          // [4][64]

    int tid = threadIdx.x, lane = tid & 31, wid = tid >> 5;
    int group = wid >> 2;            // 0 = U, 1 = V
    int warp_m = wid & 1;            // 2 row groups of 32
    int warp_n = (wid >> 1) & 1;     // 2 col groups of 64
    int m0 = blockIdx.x * 64;

    for (int r = tid; r < 64; r += 256) {
        int row = m0 + r;
        int rc = (row < E1) ? row : 0;
        s_row[0 * 64 + r] = (row < E1) ? e1e2[row] : 0;
        s_row[1 * 64 + r] = (row < E1) ? src1[row] : 0;
        s_row[2 * 64 + r] = (row < E1) ? dst1[row] : 0;
        s_row[3 * 64 + r] = rc;
    }
    __syncthreads();

    const int wrowU[4] = {0, 384, 512, 768};
    const int wrowV[4] = {128, 0, 640, 800};

    auto copy_chunk = [&](int kc, int st) {
        int seg = kc >> 2;
        int off = (kc & 3) * 32;
        const float* base; int pitch;
        if (seg == 0)      { base = t_e2; pitch = H; }
        else if (seg == 1) { base = h;    pitch = H; }
        else if (seg == 2) { base = h;    pitch = H; }
        else               { base = rbf1; pitch = 32; }
#pragma unroll
        for (int it = 0; it < 2; it++) {
            int pos = tid + it * 256;
            int r = pos >> 3, c4 = pos & 7;
            const float* src = base + (size_t)s_row[seg * 64 + r] * pitch + off + c4 * 4;
            cpa16(&As[st][r][c4 * 4], src);
        }
        const float* WU = W + (size_t)(wrowU[seg] + off) * H;
#pragma unroll
        for (int it = 0; it < 4; it++) {
            int pos = tid + it * 256;
            int r = pos >> 5, c4 = pos & 31;
            cpa16(&BU[st][r][c4 * 4], WU + r * H + c4 * 4);
        }
        if (seg != 1) {
            const float* WV = W + (size_t)(wrowV[seg] + off) * H;
#pragma unroll
            for (int it = 0; it < 4; it++) {
                int pos = tid + it * 256;
                int r = pos >> 5, c4 = pos & 31;
                cpa16(&BV[st][r][c4 * 4], WV + r * H + c4 * 4);
            }
        }
    };

    float C[2][8][4] = {};
    const int TOT = 13;

    copy_chunk(0, 0);
    CP_COMMIT();
    for (int kc = 0; kc < TOT; kc++) {
        if (kc + 1 < TOT) { copy_chunk(kc + 1, (kc + 1) & 1); CP_COMMIT(); CP_WAIT1(); }
        else              { CP_WAIT0(); }
        __syncthreads();
        int st = kc & 1;
        int seg = kc >> 2;
        if (group == 0 || seg != 1) {
            float(*Bsrc)[132] = group ? BV[st] : BU[st];
#pragma unroll
            for (int ks = 0; ks < 4; ks++) {
                int k0 = ks * 8;
                unsigned a[2][4];
#pragma unroll
                for (int mt = 0; mt < 2; mt++) {
                    int rb = warp_m * 32 + mt * 16 + (lane >> 2);
                    int cb = k0 + (lane & 3);
                    a[mt][0] = __float_as_uint(As[st][rb][cb]);
                    a[mt][1] = __float_as_uint(As[st][rb + 8][cb]);
                    a[mt][2] = __float_as_uint(As[st][rb][cb + 4]);
                    a[mt][3] = __float_as_uint(As[st][rb + 8][cb + 4]);
                }
#pragma unroll
                for (int nt = 0; nt < 8; nt++) {
                    int nb = warp_n * 64 + nt * 8 + (lane >> 2);
                    unsigned b0 = __float_as_uint(Bsrc[k0 + (lane & 3)][nb]);
                    unsigned b1 = __float_as_uint(Bsrc[k0 + (lane & 3) + 4][nb]);
                    mma_tf32(C[0][nt], a[0], b0, b1);
                    mma_tf32(C[1][nt], a[1], b0, b1);
                }
            }
        }
        __syncthreads();
    }

    float* outp = group ? outV : outU;
#pragma unroll
    for (int mt = 0; mt < 2; mt++) {
        int r0 = m0 + warp_m * 32 + mt * 16 + (lane >> 2);
#pragma unroll
        for (int nt = 0; nt < 8; nt++) {
            int cb = warp_n * 64 + nt * 8 + 2 * (lane & 3);
            if (r0 < E1)
                *(float2*)&outp[(size_t)r0 * H + cb] =
                    make_float2(C[mt][nt][0], C[mt][nt][1]);
            if (r0 + 8 < E1)
                *(float2*)&outp[(size_t)(r0 + 8) * H + cb] =
                    make_float2(C[mt][nt][2], C[mt][nt][3]);
        }
    }
}

// -------------- generic gathered GEMM (used for Z) ------------------------
struct GSpec {
    const float* base[4];
    const int*   idx[4];
    int          pitch[4];
    int          width[4];
    int          wrow[4];
    int          nseg;
};

__global__ void __launch_bounds__(NT) k_proj(GSpec g, int R, const float* __restrict__ W,
                                             float* __restrict__ out) {
    __shared__ float As[64][33];
    __shared__ float Bs[32][132];
    __shared__ int   s_row[4][64];
    int tid = threadIdx.x, lane = tid & 31, wid = tid >> 5;
    int warp_m = wid & 1, warp_n = wid >> 1;
    int m0 = blockIdx.x * 64;

    for (int s = 0; s < g.nseg; s++)
        for (int r = tid; r < 64; r += NT) {
            int row = m0 + r;
            s_row[s][r] = (row < R) ? (g.idx[s] ? g.idx[s][row] : row) : 0;
        }
    __syncthreads();

    float C[2][4][4] = {};
    int tot = 0;
    for (int s = 0; s < g.nseg; s++) tot += g.width[s] >> 5;

    int seg = 0, segch = 0;
    for (int kc = 0; kc < tot; kc++) {
        int off = segch * 32;
        const float* base = g.base[seg];
        int pitch = g.pitch[seg];
        const float* Wc = W + (size_t)(g.wrow[seg] + off) * H;
#pragma unroll
        for (int it = 0; it < 8; it++) {
            int pos = tid + it * NT;
            int r = pos >> 5, c = pos & 31;
            As[r][c] = to_tf32(base[(size_t)s_row[seg][r] * pitch + off + c]);
        }
#pragma unroll
        for (int it = 0; it < 16; it++) {
            int pos = tid + it * NT;
            int r = pos >> 7, c = pos & 127;
            Bs[r][c] = to_tf32(Wc[pos]);
        }
        __syncthreads();
#pragma unroll
        for (int ks = 0; ks < 4; ks++) {
            int k0 = ks * 8;
            unsigned a[2][4];
#pragma unroll
            for (int mt = 0; mt < 2; mt++) {
                int rb = warp_m * 32 + mt * 16 + (lane >> 2);
                int cb = k0 + (lane & 3);
                a[mt][0] = __float_as_uint(As[rb][cb]);
                a[mt][1] = __float_as_uint(As[rb + 8][cb]);
                a[mt][2] = __float_as_uint(As[rb][cb + 4]);
                a[mt][3] = __float_as_uint(As[rb + 8][cb + 4]);
            }
#pragma unroll
            for (int nt = 0; nt < 4; nt++) {
                int nb = warp_n * 32 + nt * 8 + (lane >> 2);
                unsigned b0 = __float_as_uint(Bs[k0 + (lane & 3)][nb]);
                unsigned b1 = __float_as_uint(Bs[k0 + (lane & 3) + 4][nb]);
                mma_tf32(C[0][nt], a[0], b0, b1);
                mma_tf32(C[1][nt], a[1], b0, b1);
            }
        }
        __syncthreads();
        segch++;
        if ((segch << 5) >= g.width[seg]) { seg++; segch = 0; }
    }

#pragma unroll
    for (int mt = 0; mt < 2; mt++) {
        int r0 = warp_m * 32 + mt * 16 + (lane >> 2);
#pragma unroll
        for (int nt = 0; nt < 4; nt++) {
            int cb = warp_n * 32 + nt * 8 + 2 * (lane & 3);
            int row = m0 + r0;
            if (row < R)
                *(float2*)&out[(size_t)row * H + cb] = make_float2(C[mt][nt][0], C[mt][nt][1]);
            if (row + 8 < R)
                *(float2*)&out[(size_t)(row + 8) * H + cb] = make_float2(C[mt][nt][2], C[mt][nt][3]);
        }
    }
}

// ---- FUSED: wedge segment-sum (into smem) + 3-stage GEMM + gated output --
//  Phase A: Ss[r] = sum_w silu(U[eik]+V[ekj]+Z[q]+c*w864+b1), warp = 8 rows
//  Phase B (12-chunk cp.async pipeline):
//   chunks 0-3:  C  = S @ W2      (A = Ss)
//   chunks 4-7:  C2 = m @ wgw     (A = Ms, written at kc==3; Ss reloaded w/ t)
//   chunks 8-11: C3 = t @ wgt     (A = Ss)
//  out = t + sigmoid(C2+bgw) * tanh(C3+bgt)
__global__ void __launch_bounds__(NT) k_sfinal(const float* __restrict__ t_e2,
                                               const float* __restrict__ sph,
                                               const float* __restrict__ w1,
                                               const float* __restrict__ b1,
                                               const float* __restrict__ w2,
                                               const float* __restrict__ b2,
                                               const float* __restrict__ wgw,
                                               const float* __restrict__ bgw,
                                               const float* __restrict__ wgt,
                                               const float* __restrict__ bgt,
                                               int E2, float* __restrict__ out) {
    extern __shared__ float sm[];
    float(*Ss)[132] = (float(*)[132])sm;                           // 64 x 132
    float(*Ms)[132] = (float(*)[132])(sm + 64 * 132);              // 64 x 132
    float(*Bs)[32][132] = (float(*)[32][132])(sm + 2 * 64 * 132);  // 2 stages
    __shared__ int s_cnt[64];

    int tid = threadIdx.x, lane = tid & 31, wid = tid >> 5;
    int warp_m = wid & 1, warp_n = wid >> 1;
    int m0 = blockIdx.x * 64;

    auto loadB = [&](int kc, int st) {
        const float* Wc;
        if (kc < 4)      Wc = w2  + (size_t)kc * 32 * H;
        else if (kc < 8) Wc = wgw + (size_t)(kc - 4) * 32 * H;
        else             Wc = wgt + (size_t)(kc - 8) * 32 * H;
#pragma unroll
        for (int it = 0; it < 4; it++) {
            int pos = tid + it * NT;
            int r = pos >> 5, c4 = pos & 31;
            cpa16(&Bs[st][r][c4 * 4], Wc + r * H + c4 * 4);
        }
    };

    // kick off first weight chunk; it lands while we do the wedge phase
    loadB(0, 0);
    CP_COMMIT();

    // ---- Phase A: wedge segment-sum, warp handles rows [wid*8, wid*8+8) ---
    float4 w8 = *(const float4*)&w1[(size_t)864 * H + lane * 4];
    float4 bb = *(const float4*)&b1[lane * 4];
#pragma unroll 1
    for (int i = 0; i < 8; i++) {
        int r = wid * 8 + i;
        int q = m0 + r;
        float4 acc = make_float4(0.f, 0.f, 0.f, 0.f);
        if (q < E2) {
            int beg = g_wptr[q], end = g_wptr[q + 1];
            if (beg > WCAP) beg = WCAP;
            if (end > WCAP) end = WCAP;
            if (lane == 0) s_cnt[r] = end - beg;
            float4 z = *(const float4*)&g_Z[(size_t)q * H + lane * 4];
            float4 u, v; float cf = 0.f;
            int w = beg;
            if (w < end) {
                int a = g_weik[w], b = g_wekj[w];
                cf = __ldg(&sph[a * 3 + 1]) * __ldg(&sph[b * 3 + 1]);
                u = *(const float4*)&g_U[(size_t)a * H + lane * 4];
                v = *(const float4*)&g_V[(size_t)b * H + lane * 4];
            }
            while (w < end) {
                float4 cu = u, cv = v; float c0 = cf;
                int nw = w + 1;
                if (nw < end) {
                    int a = g_weik[nw], b = g_wekj[nw];
                    cf = __ldg(&sph[a * 3 + 1]) * __ldg(&sph[b * 3 + 1]);
                    u = *(const float4*)&g_U[(size_t)a * H + lane * 4];
                    v = *(const float4*)&g_V[(size_t)b * H + lane * 4];
                }
                float x;
                x = cu.x + cv.x + z.x + c0 * w8.x + bb.x; acc.x += x / (1.f + __expf(-x));
                x = cu.y + cv.y + z.y + c0 * w8.y + bb.y; acc.y += x / (1.f + __expf(-x));
                x = cu.z + cv.z + z.z + c0 * w8.z + bb.z; acc.z += x / (1.f + __expf(-x));
                x = cu.w + cv.w + z.w + c0 * w8.w + bb.w; acc.w += x / (1.f + __expf(-x));
                w = nw;
            }
        } else if (lane == 0) {
            s_cnt[r] = 0;
        }
        *(float4*)&Ss[r][lane * 4] = acc;
    }
    __syncthreads();

    // ---- Phase B: unified 12-chunk pipelined 3-stage GEMM ----
    float C[2][4][4] = {};
    float C2[2][4][4] = {};
    float C3[2][4][4] = {};
    for (int kc = 0; kc < 12; kc++) {
        if (kc + 1 < 12) { loadB(kc + 1, (kc + 1) & 1); CP_COMMIT(); CP_WAIT1(); }
        else             { CP_WAIT0(); }
        __syncthreads();
        int st = kc & 1;
        int stage = kc >> 2;
        int kcol = (kc & 3) * 32;
        float(*Asrc)[132] = (stage == 1) ? Ms : Ss;
#pragma unroll
        for (int ks = 0; ks < 4; ks++) {
            int k0 = kcol + ks * 8;
            int kb = ks * 8;
            unsigned a[2][4];
#pragma unroll
            for (int mt = 0; mt < 2; mt++) {
                int rb = warp_m * 32 + mt * 16 + (lane >> 2);
                int cb = k0 + (lane & 3);
                a[mt][0] = __float_as_uint(Asrc[rb][cb]);
                a[mt][1] = __float_as_uint(Asrc[rb + 8][cb]);
                a[mt][2] = __float_as_uint(Asrc[rb][cb + 4]);
                a[mt][3] = __float_as_uint(Asrc[rb + 8][cb + 4]);
            }
#pragma unroll
            for (int nt = 0; nt < 4; nt++) {
                int nb = warp_n * 32 + nt * 8 + (lane >> 2);
                unsigned b0 = __float_as_uint(Bs[st][kb + (lane & 3)][nb]);
                unsigned b1 = __float_as_uint(Bs[st][kb + (lane & 3) + 4][nb]);
                if (stage == 0)      { mma_tf32(C[0][nt],  a[0], b0, b1); mma_tf32(C[1][nt],  a[1], b0, b1); }
                else if (stage == 1) { mma_tf32(C2[0][nt], a[0], b0, b1); mma_tf32(C2[1][nt], a[1], b0, b1); }
                else                 { mma_tf32(C3[0][nt], a[0], b0, b1); mma_tf32(C3[1][nt], a[1], b0, b1); }
            }
        }
        __syncthreads();
        if (kc == 3) {
            // Ms = m = C + cnt*b2 ; reload Ss with t tile (stage 2 + epilogue)
#pragma unroll
            for (int mt = 0; mt < 2; mt++) {
                int r0 = warp_m * 32 + mt * 16 + (lane >> 2);
                float cn0 = (float)s_cnt[r0], cn1 = (float)s_cnt[r0 + 8];
#pragma unroll
                for (int nt = 0; nt < 4; nt++) {
                    int cb = warp_n * 32 + nt * 8 + 2 * (lane & 3);
                    Ms[r0][cb]         = C[mt][nt][0] + cn0 * b2[cb];
                    Ms[r0][cb + 1]     = C[mt][nt][1] + cn0 * b2[cb + 1];
                    Ms[r0 + 8][cb]     = C[mt][nt][2] + cn1 * b2[cb];
                    Ms[r0 + 8][cb + 1] = C[mt][nt][3] + cn1 * b2[cb + 1];
                }
            }
#pragma unroll
            for (int it = 0; it < 8; it++) {
                int pos = tid + it * NT;
                int r = pos >> 5, c4 = pos & 31;
                int row = m0 + r;
                float4 v = (row < E2) ? *(const float4*)&t_e2[(size_t)row * H + c4 * 4]
                                      : make_float4(0.f, 0.f, 0.f, 0.f);
                *(float4*)&Ss[r][c4 * 4] = v;
            }
            __syncthreads();
        }
    }

    // epilogue: out = t (from Ss) + sigmoid(C2+bgw) * tanh(C3+bgt)
#pragma unroll
    for (int mt = 0; mt < 2; mt++) {
        int rl = warp_m * 32 + mt * 16 + (lane >> 2);
#pragma unroll
        for (int nt = 0; nt < 4; nt++) {
            int cb = warp_n * 32 + nt * 8 + 2 * (lane & 3);
#pragma unroll
            for (int half = 0; half < 2; half++) {
                int row = m0 + rl + half * 8;
                if (row >= E2) continue;
#pragma unroll
                for (int e = 0; e < 2; e++) {
                    int col = cb + e;
                    float gw = C2[mt][nt][half * 2 + e] + bgw[col];
                    float gt = C3[mt][nt][half * 2 + e] + bgt[col];
                    float sig = 1.f / (1.f + __expf(-gw));
                    out[(size_t)row * H + col] =
                        Ss[rl + half * 8][col] + sig * tanhf(gt);
                }
            }
        }
    }
}

// --------------------------------------------------------------------------
extern "C" void kernel_launch(void* const* d_in, const int* in_sizes, int n_in,
                              void* d_out, int out_size) {
    const float* t_e2 = (const float*)d_in[0];
    const float* h    = (const float*)d_in[1];
    const int*   ei1  = (const int*)d_in[2];
    const int*   ei2  = (const int*)d_in[3];
    const int*   e1e2 = (const int*)d_in[4];
    const float* rbf1 = (const float*)d_in[7];
    const float* rbf2 = (const float*)d_in[8];
    const float* sph  = (const float*)d_in[9];
    const int*   nn_p = (const int*)d_in[10];
    const float* w1   = (const float*)d_in[11];
    const float* b1   = (const float*)d_in[12];
    const float* w2   = (const float*)d_in[13];
    const float* b2   = (const float*)d_in[14];
    const float* wgw  = (const float*)d_in[15];
    const float* bgw  = (const float*)d_in[16];
    const float* wgt  = (const float*)d_in[17];
    const float* bgt  = (const float*)d_in[18];

    int E1 = in_sizes[4];
    int E2 = in_sizes[0] / H;
    const int* src1 = ei1;
    const int* dst1 = ei1 + E1;
    const int* src2 = ei2;
    const int* dst2 = ei2 + E2;

    float *pU, *pV, *pZ;
    cudaGetSymbolAddress((void**)&pU, g_U);
    cudaGetSymbolAddress((void**)&pV, g_V);
    cudaGetSymbolAddress((void**)&pZ, g_Z);

    size_t fsmem = (size_t)(2 * 64 * 132 + 2 * 32 * 132) * 4;
    cudaFuncSetAttribute(k_sfinal, cudaFuncAttributeMaxDynamicSharedMemorySize, (int)fsmem);
    size_t uvsmem = (size_t)(2 * 64 * 36 + 4 * 32 * 132) * 4 + 4 * 64 * sizeof(int);
    cudaFuncSetAttribute(k_projUV, cudaFuncAttributeMaxDynamicSharedMemorySize, (int)uvsmem);

    static cudaStream_t s1 = nullptr, s2 = nullptr;
    static cudaEvent_t evRoot = nullptr, ev1 = nullptr, ev2 = nullptr;
    if (!s1) {
        cudaStreamCreateWithFlags(&s1, cudaStreamNonBlocking);
        cudaStreamCreateWithFlags(&s2, cudaStreamNonBlocking);
        cudaEventCreateWithFlags(&evRoot, cudaEventDisableTiming);
        cudaEventCreateWithFlags(&ev1, cudaEventDisableTiming);
        cudaEventCreateWithFlags(&ev2, cudaEventDisableTiming);
    }

    // ---- fork: projections run concurrently with wedge-list construction --
    cudaEventRecord(evRoot, 0);
    cudaStreamWaitEvent(s1, evRoot, 0);
    cudaStreamWaitEvent(s2, evRoot, 0);

    // s1: merged U+V projection (13 chunks, starts immediately)
    k_projUV<<<(E1 + 63) / 64, 256, uvsmem, s1>>>(t_e2, h, e1e2, src1, dst1,
                                                  rbf1, E1, w1, pU, pV);
    cudaEventRecord(ev1, s1);

    // s2: Z projection
    {
        GSpec gz;
        gz.nseg = 2;
        gz.base[0] = t_e2; gz.idx[0] = nullptr; gz.pitch[0] = H;  gz.width[0] = 128; gz.wrow[0] = 256;
        gz.base[1] = rbf2; gz.idx[1] = nullptr; gz.pitch[1] = 32; gz.width[1] = 32;  gz.wrow[1] = 832;
        gz.base[2] = t_e2; gz.idx[2] = nullptr; gz.pitch[2] = H;  gz.width[2] = 0;   gz.wrow[2] = 0;
        gz.base[3] = t_e2; gz.idx[3] = nullptr; gz.pitch[3] = H;  gz.width[3] = 0;   gz.wrow[3] = 0;
        k_proj<<<(E2 + 63) / 64, NT, 0, s2>>>(gz, E2, w1, pZ);
    }
    cudaEventRecord(ev2, s2);

    // default stream: wedge-list construction chain
    k_ptr<<<(NMAX + 1 + NT - 1) / NT, NT>>>(src1, E1, nn_p);
    k_count<<<(E2 + NT - 1) / NT, NT>>>(src2, dst2, dst1, E2);
    int nscan = (E2 + 2047) / 2048;
    k_scan_part<<<nscan, NT>>>(E2);
    k_scan_top<<<1, 32>>>(nscan, E2);
    k_scan_write<<<nscan, NT>>>(E2);
    k_fill<<<(E2 + NT - 1) / NT, NT>>>(src2, dst2, dst1, E2);

    // ---- join ----
    cudaStreamWaitEvent(0, ev1, 0);
    cudaStreamWaitEvent(0, ev2, 0);

    // fused: wedge segment-sum + 3-stage GEMM + gated output
    k_sfinal<<<(E2 + 63) / 64, NT, fsmem>>>(t_e2, sph, w1, b1, w2, b2,
                                            wgw, bgw, wgt, bgt, E2,
                                            (float*)d_out);
}

// round 13
// speedup vs baseline: 1.1044x; 1.1044x over previous
#include <cuda_runtime.h>
#include <cuda_fp16.h>

#define H     128
#define NT    256
#define NMAX  10016
#define E1MAX 80000
#define E2MAX 80000
#define WCAP  (E1MAX*16)

// ------- scratch (static device globals; no runtime allocation) ----------
__device__ int   g_ptr[NMAX + 2];
__device__ int   g_cnt[E2MAX];
__device__ int   g_part[128];
__device__ int   g_wptr[E2MAX + 1];
__device__ int   g_weik[WCAP];
__device__ int   g_wekj[WCAP];
__device__ float g_U[(size_t)E1MAX * H];
__device__ float g_V[(size_t)E1MAX * H];
__device__ float g_Z[(size_t)E2MAX * H];
__device__ float g_S[(size_t)E2MAX * H];

// ------------------------- helpers ---------------------------------------
__device__ __forceinline__ float to_tf32(float x) {
    unsigned u;
    asm("cvt.rna.tf32.f32 %0, %1;" : "=r"(u) : "f"(x));
    return __uint_as_float(u);
}

__device__ __forceinline__ void mma_tf32(float c[4], const unsigned a[4],
                                         unsigned b0, unsigned b1) {
    asm volatile(
        "mma.sync.aligned.m16n8k8.row.col.f32.tf32.tf32.f32 "
        "{%0,%1,%2,%3}, {%4,%5,%6,%7}, {%8,%9}, {%0,%1,%2,%3};"
        : "+f"(c[0]), "+f"(c[1]), "+f"(c[2]), "+f"(c[3])
        : "r"(a[0]), "r"(a[1]), "r"(a[2]), "r"(a[3]), "r"(b0), "r"(b1));
}

// fp16 mma m16n8k16: C (fp32) layout identical to m16n8k8
__device__ __forceinline__ void mma_f16(float c[4], const unsigned a[4],
                                        unsigned b0, unsigned b1) {
    asm volatile(
        "mma.sync.aligned.m16n8k16.row.col.f32.f16.f16.f32 "
        "{%0,%1,%2,%3}, {%4,%5,%6,%7}, {%8,%9}, {%0,%1,%2,%3};"
        : "+f"(c[0]), "+f"(c[1]), "+f"(c[2]), "+f"(c[3])
        : "r"(a[0]), "r"(a[1]), "r"(a[2]), "r"(a[3]), "r"(b0), "r"(b1));
}

__device__ __forceinline__ unsigned pack2(float lo, float hi) {
    __half2 h = __floats2half2_rn(lo, hi);
    return *reinterpret_cast<unsigned*>(&h);
}

__device__ __forceinline__ void cpa16(void* sdst, const void* gsrc) {
    unsigned s = (unsigned)__cvta_generic_to_shared(sdst);
    asm volatile("cp.async.cg.shared.global [%0], [%1], 16;\n" :: "r"(s), "l"(gsrc));
}
#define CP_COMMIT() asm volatile("cp.async.commit_group;\n")
#define CP_WAIT0()  asm volatile("cp.async.wait_group 0;\n")
#define CP_WAIT1()  asm volatile("cp.async.wait_group 1;\n")

// ---------------- CSR ptr: g_ptr[v] = lower_bound(src1, v) ---------------
__global__ void k_ptr(const int* __restrict__ src1, int E1, const int* __restrict__ nn_p) {
    int v = blockIdx.x * blockDim.x + threadIdx.x;
    int nn = *nn_p;
    if (v > nn || v > NMAX) return;
    int lo = 0, hi = E1;
    while (lo < hi) { int mid = (lo + hi) >> 1; if (src1[mid] < v) lo = mid + 1; else hi = mid; }
    g_ptr[v] = lo;
}

// ------------- per-e2-edge wedge count (sorted-by-eij build) --------------
__global__ void k_count(const int* __restrict__ src2, const int* __restrict__ dst2,
                        const int* __restrict__ dst1, int E2) {
    int q = blockIdx.x * blockDim.x + threadIdx.x;
    if (q >= E2) return;
    int i = src2[q], j = dst2[q];
    int c = 0;
    if (i != j) {
        int b0 = g_ptr[i], e0 = g_ptr[i + 1];
        for (int t = b0; t < e0; t++) {
            int k = dst1[t];
            if (k == i || k == j) continue;
            int b1 = g_ptr[k], e1 = g_ptr[k + 1];
            for (int u = b1; u < e1; u++)
                if (dst1[u] == j) c++;
        }
    }
    g_cnt[q] = c;
}

// ----------------------- 3-phase exclusive scan ---------------------------
__global__ void k_scan_part(int n) {
    int blk = blockIdx.x, tid = threadIdx.x, lane = tid & 31, wid = tid >> 5;
    int base = blk * 2048 + tid * 8;
    int s = 0;
#pragma unroll
    for (int i = 0; i < 8; i++) { int idx = base + i; if (idx < n) s += g_cnt[idx]; }
#pragma unroll
    for (int off = 16; off > 0; off >>= 1) s += __shfl_down_sync(0xffffffffu, s, off);
    __shared__ int red[8];
    if (lane == 0) red[wid] = s;
    __syncthreads();
    if (tid == 0) {
        int tot = 0;
#pragma unroll
        for (int w = 0; w < 8; w++) tot += red[w];
        g_part[blk] = tot;
    }
}
__global__ void k_scan_top(int nb, int n) {
    if (threadIdx.x == 0) {
        int acc = 0;
        for (int b = 0; b < nb; b++) { int v = g_part[b]; g_part[b] = acc; acc += v; }
        g_wptr[n] = acc;
    }
}
__global__ void k_scan_write(int n) {
    int blk = blockIdx.x, tid = threadIdx.x, lane = tid & 31, wid = tid >> 5;
    int base = blk * 2048 + tid * 8;
    int v[8]; int s = 0;
#pragma unroll
    for (int i = 0; i < 8; i++) {
        int idx = base + i;
        v[i] = (idx < n) ? g_cnt[idx] : 0;
        s += v[i];
    }
    int x = s;
#pragma unroll
    for (int off = 1; off < 32; off <<= 1) {
        int t = __shfl_up_sync(0xffffffffu, x, off);
        if (lane >= off) x += t;
    }
    __shared__ int wsum[8];
    if (lane == 31) wsum[wid] = x;
    __syncthreads();
    __shared__ int wexc[8];
    if (tid == 0) {
        int acc = 0;
#pragma unroll
        for (int w = 0; w < 8; w++) { wexc[w] = acc; acc += wsum[w]; }
    }
    __syncthreads();
    int run = g_part[blk] + wexc[wid] + x - s;
#pragma unroll
    for (int i = 0; i < 8; i++) {
        int idx = base + i;
        if (idx < n) g_wptr[idx] = run;
        run += v[i];
    }
}

__global__ void k_fill(const int* __restrict__ src2, const int* __restrict__ dst2,
                       const int* __restrict__ dst1, int E2) {
    int q = blockIdx.x * blockDim.x + threadIdx.x;
    if (q >= E2) return;
    int i = src2[q], j = dst2[q];
    if (i == j) return;
    int pos = g_wptr[q];
    int b0 = g_ptr[i], e0 = g_ptr[i + 1];
    for (int t = b0; t < e0; t++) {
        int k = dst1[t];
        if (k == i || k == j) continue;
        int b1 = g_ptr[k], e1 = g_ptr[k + 1];
        for (int u = b1; u < e1; u++)
            if (dst1[u] == j) {
                if (pos < WCAP) { g_weik[pos] = t; g_wekj[pos] = u; }
                pos++;
            }
    }
}

// ---------- merged U+V projection (M=64, occ 2, cp.async, fp16 mma) -------
// 13 chunks: seg0 t_e2[e1e2], seg1 h[src] (U only), seg2 h[dst], seg3 rbf1.
// fp32 tiles in smem; fragments converted to fp16 in registers (same 10-bit
// mantissa as tf32); mma.m16n8k16.f16 = 2x MAC/instr of tf32 m16n8k8.
__global__ void __launch_bounds__(256, 2) k_projUV(
    const float* __restrict__ t_e2, const float* __restrict__ h,
    const int* __restrict__ e1e2, const int* __restrict__ src1,
    const int* __restrict__ dst1, const float* __restrict__ rbf1,
    int E1, const float* __restrict__ W,
    float* __restrict__ outU, float* __restrict__ outV) {
    extern __shared__ float sm[];
    float(*As)[64][36]  = (float(*)[64][36])sm;                    // 2 stages
    float(*BU)[32][132] = (float(*)[32][132])(sm + 2 * 64 * 36);
    float(*BV)[32][132] = (float(*)[32][132])(sm + 2 * 64 * 36 + 2 * 32 * 132);
    int* s_row = (int*)(sm + 2 * 64 * 36 + 4 * 32 * 132);          // [4][64]

    int tid = threadIdx.x, lane = tid & 31, wid = tid >> 5;
    int group = wid >> 2;            // 0 = U, 1 = V
    int warp_m = wid & 1;            // 2 row groups of 32
    int warp_n = (wid >> 1) & 1;     // 2 col groups of 64
    int m0 = blockIdx.x * 64;

    for (int r = tid; r < 64; r += 256) {
        int row = m0 + r;
        int rc = (row < E1) ? row : 0;
        s_row[0 * 64 + r] = (row < E1) ? e1e2[row] : 0;
        s_row[1 * 64 + r] = (row < E1) ? src1[row] : 0;
        s_row[2 * 64 + r] = (row < E1) ? dst1[row] : 0;
        s_row[3 * 64 + r] = rc;
    }
    __syncthreads();

    const int wrowU[4] = {0, 384, 512, 768};
    const int wrowV[4] = {128, 0, 640, 800};

    auto copy_chunk = [&](int kc, int st) {
        int seg = kc >> 2;
        int off = (kc & 3) * 32;
        const float* base; int pitch;
        if (seg == 0)      { base = t_e2; pitch = H; }
        else if (seg == 1) { base = h;    pitch = H; }
        else if (seg == 2) { base = h;    pitch = H; }
        else               { base = rbf1; pitch = 32; }
#pragma unroll
        for (int it = 0; it < 2; it++) {
            int pos = tid + it * 256;
            int r = pos >> 3, c4 = pos & 7;
            const float* src = base + (size_t)s_row[seg * 64 + r] * pitch + off + c4 * 4;
            cpa16(&As[st][r][c4 * 4], src);
        }
        const float* WU = W + (size_t)(wrowU[seg] + off) * H;
#pragma unroll
        for (int it = 0; it < 4; it++) {
            int pos = tid + it * 256;
            int r = pos >> 5, c4 = pos & 31;
            cpa16(&BU[st][r][c4 * 4], WU + r * H + c4 * 4);
        }
        if (seg != 1) {
            const float* WV = W + (size_t)(wrowV[seg] + off) * H;
#pragma unroll
            for (int it = 0; it < 4; it++) {
                int pos = tid + it * 256;
                int r = pos >> 5, c4 = pos & 31;
                cpa16(&BV[st][r][c4 * 4], WV + r * H + c4 * 4);
            }
        }
    };

    float C[2][8][4] = {};
    const int TOT = 13;

    copy_chunk(0, 0);
    CP_COMMIT();
    for (int kc = 0; kc < TOT; kc++) {
        if (kc + 1 < TOT) { copy_chunk(kc + 1, (kc + 1) & 1); CP_COMMIT(); CP_WAIT1(); }
        else              { CP_WAIT0(); }
        __syncthreads();
        int st = kc & 1;
        int seg = kc >> 2;
        if (group == 0 || seg != 1) {
            float(*Bsrc)[132] = group ? BV[st] : BU[st];
            int c2 = (lane & 3) * 2;
#pragma unroll
            for (int ks2 = 0; ks2 < 2; ks2++) {
                int kb = ks2 * 16;
                unsigned a[2][4];
#pragma unroll
                for (int mt = 0; mt < 2; mt++) {
                    int rb = warp_m * 32 + mt * 16 + (lane >> 2);
                    a[mt][0] = pack2(As[st][rb][kb + c2],         As[st][rb][kb + c2 + 1]);
                    a[mt][1] = pack2(As[st][rb + 8][kb + c2],     As[st][rb + 8][kb + c2 + 1]);
                    a[mt][2] = pack2(As[st][rb][kb + c2 + 8],     As[st][rb][kb + c2 + 9]);
                    a[mt][3] = pack2(As[st][rb + 8][kb + c2 + 8], As[st][rb + 8][kb + c2 + 9]);
                }
#pragma unroll
                for (int nt = 0; nt < 8; nt++) {
                    int nb = warp_n * 64 + nt * 8 + (lane >> 2);
                    unsigned b0 = pack2(Bsrc[kb + c2][nb],     Bsrc[kb + c2 + 1][nb]);
                    unsigned b1 = pack2(Bsrc[kb + c2 + 8][nb], Bsrc[kb + c2 + 9][nb]);
                    mma_f16(C[0][nt], a[0], b0, b1);
                    mma_f16(C[1][nt], a[1], b0, b1);
                }
            }
        }
        __syncthreads();
    }

    float* outp = group ? outV : outU;
#pragma unroll
    for (int mt = 0; mt < 2; mt++) {
        int r0 = m0 + warp_m * 32 + mt * 16 + (lane >> 2);
#pragma unroll
        for (int nt = 0; nt < 8; nt++) {
            int cb = warp_n * 64 + nt * 8 + 2 * (lane & 3);
            if (r0 < E1)
                *(float2*)&outp[(size_t)r0 * H + cb] =
                    make_float2(C[mt][nt][0], C[mt][nt][1]);
            if (r0 + 8 < E1)
                *(float2*)&outp[(size_t)(r0 + 8) * H + cb] =
                    make_float2(C[mt][nt][2], C[mt][nt][3]);
        }
    }
}

// -------------- generic gathered GEMM (used for Z) ------------------------
struct GSpec {
    const float* base[4];
    const int*   idx[4];
    int          pitch[4];
    int          width[4];
    int          wrow[4];
    int          nseg;
};

__global__ void __launch_bounds__(NT) k_proj(GSpec g, int R, const float* __restrict__ W,
                                             float* __restrict__ out) {
    __shared__ float As[64][33];
    __shared__ float Bs[32][132];
    __shared__ int   s_row[4][64];
    int tid = threadIdx.x, lane = tid & 31, wid = tid >> 5;
    int warp_m = wid & 1, warp_n = wid >> 1;
    int m0 = blockIdx.x * 64;

    for (int s = 0; s < g.nseg; s++)
        for (int r = tid; r < 64; r += NT) {
            int row = m0 + r;
            s_row[s][r] = (row < R) ? (g.idx[s] ? g.idx[s][row] : row) : 0;
        }
    __syncthreads();

    float C[2][4][4] = {};
    int tot = 0;
    for (int s = 0; s < g.nseg; s++) tot += g.width[s] >> 5;

    int seg = 0, segch = 0;
    for (int kc = 0; kc < tot; kc++) {
        int off = segch * 32;
        const float* base = g.base[seg];
        int pitch = g.pitch[seg];
        const float* Wc = W + (size_t)(g.wrow[seg] + off) * H;
#pragma unroll
        for (int it = 0; it < 8; it++) {
            int pos = tid + it * NT;
            int r = pos >> 5, c = pos & 31;
            As[r][c] = to_tf32(base[(size_t)s_row[seg][r] * pitch + off + c]);
        }
#pragma unroll
        for (int it = 0; it < 16; it++) {
            int pos = tid + it * NT;
            int r = pos >> 7, c = pos & 127;
            Bs[r][c] = to_tf32(Wc[pos]);
        }
        __syncthreads();
#pragma unroll
        for (int ks = 0; ks < 4; ks++) {
            int k0 = ks * 8;
            unsigned a[2][4];
#pragma unroll
            for (int mt = 0; mt < 2; mt++) {
                int rb = warp_m * 32 + mt * 16 + (lane >> 2);
                int cb = k0 + (lane & 3);
                a[mt][0] = __float_as_uint(As[rb][cb]);
                a[mt][1] = __float_as_uint(As[rb + 8][cb]);
                a[mt][2] = __float_as_uint(As[rb][cb + 4]);
                a[mt][3] = __float_as_uint(As[rb + 8][cb + 4]);
            }
#pragma unroll
            for (int nt = 0; nt < 4; nt++) {
                int nb = warp_n * 32 + nt * 8 + (lane >> 2);
                unsigned b0 = __float_as_uint(Bs[k0 + (lane & 3)][nb]);
                unsigned b1 = __float_as_uint(Bs[k0 + (lane & 3) + 4][nb]);
                mma_tf32(C[0][nt], a[0], b0, b1);
                mma_tf32(C[1][nt], a[1], b0, b1);
            }
        }
        __syncthreads();
        segch++;
        if ((segch << 5) >= g.width[seg]) { seg++; segch = 0; }
    }

#pragma unroll
    for (int mt = 0; mt < 2; mt++) {
        int r0 = warp_m * 32 + mt * 16 + (lane >> 2);
#pragma unroll
        for (int nt = 0; nt < 4; nt++) {
            int cb = warp_n * 32 + nt * 8 + 2 * (lane & 3);
            int row = m0 + r0;
            if (row < R)
                *(float2*)&out[(size_t)row * H + cb] = make_float2(C[mt][nt][0], C[mt][nt][1]);
            if (row + 8 < R)
                *(float2*)&out[(size_t)(row + 8) * H + cb] = make_float2(C[mt][nt][2], C[mt][nt][3]);
        }
    }
}

// ---- per-e2 hidden sum: S[q] = sum_w silu(U[eik]+V[ekj]+Z[q]+c*w864+b1) ---
__global__ void __launch_bounds__(NT) k_hsum(const float* __restrict__ sph,
                                             const float* __restrict__ w1,
                                             const float* __restrict__ b1, int E2) {
    int warp = (blockIdx.x * blockDim.x + threadIdx.x) >> 5;
    int lane = threadIdx.x & 31;
    if (warp >= E2) return;
    int q = warp;
    int beg = g_wptr[q], end = g_wptr[q + 1];
    if (beg > WCAP) beg = WCAP;
    if (end > WCAP) end = WCAP;
    float4 z  = *(const float4*)&g_Z[(size_t)q * H + lane * 4];
    float4 w8 = *(const float4*)&w1[(size_t)864 * H + lane * 4];
    float4 bb = *(const float4*)&b1[lane * 4];
    float4 acc = make_float4(0.f, 0.f, 0.f, 0.f);

    float4 u, v; float cf = 0.f;
    int w = beg;
    if (w < end) {
        int a = g_weik[w], b = g_wekj[w];
        cf = __ldg(&sph[a * 3 + 1]) * __ldg(&sph[b * 3 + 1]);
        u = *(const float4*)&g_U[(size_t)a * H + lane * 4];
        v = *(const float4*)&g_V[(size_t)b * H + lane * 4];
    }
    while (w < end) {
        float4 cu = u, cv = v; float c0 = cf;
        int nw = w + 1;
        if (nw < end) {
            int a = g_weik[nw], b = g_wekj[nw];
            cf = __ldg(&sph[a * 3 + 1]) * __ldg(&sph[b * 3 + 1]);
            u = *(const float4*)&g_U[(size_t)a * H + lane * 4];
            v = *(const float4*)&g_V[(size_t)b * H + lane * 4];
        }
        float x;
        x = cu.x + cv.x + z.x + c0 * w8.x + bb.x; acc.x += x / (1.f + __expf(-x));
        x = cu.y + cv.y + z.y + c0 * w8.y + bb.y; acc.y += x / (1.f + __expf(-x));
        x = cu.z + cv.z + z.z + c0 * w8.z + bb.z; acc.z += x / (1.f + __expf(-x));
        x = cu.w + cv.w + z.w + c0 * w8.w + bb.w; acc.w += x / (1.f + __expf(-x));
        w = nw;
    }
    *(float4*)&g_S[(size_t)q * H + lane * 4] = acc;
}

// ---- final (unified 12-chunk cp.async pipeline, tf32):
//  chunks 0-3:  C  = S @ W2      (A = Ss)
//  chunks 4-7:  C2 = m @ wgw     (A = Ms, written at kc==3; Ss reloaded w/ t)
//  chunks 8-11: C3 = t @ wgt     (A = Ss)
//  out = t + sigmoid(C2+bgw) * tanh(C3+bgt)
__global__ void __launch_bounds__(NT) k_final(const float* __restrict__ t_e2,
                                              const float* __restrict__ w2,
                                              const float* __restrict__ b2,
                                              const float* __restrict__ wgw,
                                              const float* __restrict__ bgw,
                                              const float* __restrict__ wgt,
                                              const float* __restrict__ bgt,
                                              int E2, float* __restrict__ out) {
    extern __shared__ float sm[];
    float(*Ss)[132] = (float(*)[132])sm;                           // 64 x 132
    float(*Ms)[132] = (float(*)[132])(sm + 64 * 132);              // 64 x 132
    float(*Bs)[32][132] = (float(*)[32][132])(sm + 2 * 64 * 132);  // 2 stages
    __shared__ int s_cnt[64];

    int tid = threadIdx.x, lane = tid & 31, wid = tid >> 5;
    int warp_m = wid & 1, warp_n = wid >> 1;
    int m0 = blockIdx.x * 64;

    for (int r = tid; r < 64; r += NT) {
        int row = m0 + r;
        s_cnt[r] = (row < E2) ? (g_wptr[row + 1] - g_wptr[row]) : 0;
    }
#pragma unroll
    for (int it = 0; it < 8; it++) {
        int pos = tid + it * NT;
        int r = pos >> 5, c4 = pos & 31;
        int row = m0 + r;
        float4 v = (row < E2) ? *(const float4*)&g_S[(size_t)row * H + c4 * 4]
                              : make_float4(0.f, 0.f, 0.f, 0.f);
        *(float4*)&Ss[r][c4 * 4] = v;
    }

    auto loadB = [&](int kc, int st) {
        const float* Wc;
        if (kc < 4)      Wc = w2  + (size_t)kc * 32 * H;
        else if (kc < 8) Wc = wgw + (size_t)(kc - 4) * 32 * H;
        else             Wc = wgt + (size_t)(kc - 8) * 32 * H;
#pragma unroll
        for (int it = 0; it < 4; it++) {
            int pos = tid + it * NT;
            int r = pos >> 5, c4 = pos & 31;
            cpa16(&Bs[st][r][c4 * 4], Wc + r * H + c4 * 4);
        }
    };

    float C[2][4][4] = {};
    float C2[2][4][4] = {};
    float C3[2][4][4] = {};
    loadB(0, 0);
    CP_COMMIT();
    __syncthreads();
    for (int kc = 0; kc < 12; kc++) {
        if (kc + 1 < 12) { loadB(kc + 1, (kc + 1) & 1); CP_COMMIT(); CP_WAIT1(); }
        else             { CP_WAIT0(); }
        __syncthreads();
        int st = kc & 1;
        int stage = kc >> 2;
        int kcol = (kc & 3) * 32;
        float(*Asrc)[132] = (stage == 1) ? Ms : Ss;
#pragma unroll
        for (int ks = 0; ks < 4; ks++) {
            int k0 = kcol + ks * 8;
            int kb = ks * 8;
            unsigned a[2][4];
#pragma unroll
            for (int mt = 0; mt < 2; mt++) {
                int rb = warp_m * 32 + mt * 16 + (lane >> 2);
                int cb = k0 + (lane & 3);
                a[mt][0] = __float_as_uint(Asrc[rb][cb]);
                a[mt][1] = __float_as_uint(Asrc[rb + 8][cb]);
                a[mt][2] = __float_as_uint(Asrc[rb][cb + 4]);
                a[mt][3] = __float_as_uint(Asrc[rb + 8][cb + 4]);
            }
#pragma unroll
            for (int nt = 0; nt < 4; nt++) {
                int nb = warp_n * 32 + nt * 8 + (lane >> 2);
                unsigned b0 = __float_as_uint(Bs[st][kb + (lane & 3)][nb]);
                unsigned b1 = __float_as_uint(Bs[st][kb + (lane & 3) + 4][nb]);
                if (stage == 0)      { mma_tf32(C[0][nt],  a[0], b0, b1); mma_tf32(C[1][nt],  a[1], b0, b1); }
                else if (stage == 1) { mma_tf32(C2[0][nt], a[0], b0, b1); mma_tf32(C2[1][nt], a[1], b0, b1); }
                else                 { mma_tf32(C3[0][nt], a[0], b0, b1); mma_tf32(C3[1][nt], a[1], b0, b1); }
            }
        }
        __syncthreads();
        if (kc == 3) {
#pragma unroll
            for (int mt = 0; mt < 2; mt++) {
                int r0 = warp_m * 32 + mt * 16 + (lane >> 2);
                float cn0 = (float)s_cnt[r0], cn1 = (float)s_cnt[r0 + 8];
#pragma unroll
                for (int nt = 0; nt < 4; nt++) {
                    int cb = warp_n * 32 + nt * 8 + 2 * (lane & 3);
                    Ms[r0][cb]         = C[mt][nt][0] + cn0 * b2[cb];
                    Ms[r0][cb + 1]     = C[mt][nt][1] + cn0 * b2[cb + 1];
                    Ms[r0 + 8][cb]     = C[mt][nt][2] + cn1 * b2[cb];
                    Ms[r0 + 8][cb + 1] = C[mt][nt][3] + cn1 * b2[cb + 1];
                }
            }
#pragma unroll
            for (int it = 0; it < 8; it++) {
                int pos = tid + it * NT;
                int r = pos >> 5, c4 = pos & 31;
                int row = m0 + r;
                float4 v = (row < E2) ? *(const float4*)&t_e2[(size_t)row * H + c4 * 4]
                                      : make_float4(0.f, 0.f, 0.f, 0.f);
                *(float4*)&Ss[r][c4 * 4] = v;
            }
            __syncthreads();
        }
    }

#pragma unroll
    for (int mt = 0; mt < 2; mt++) {
        int rl = warp_m * 32 + mt * 16 + (lane >> 2);
#pragma unroll
        for (int nt = 0; nt < 4; nt++) {
            int cb = warp_n * 32 + nt * 8 + 2 * (lane & 3);
#pragma unroll
            for (int half = 0; half < 2; half++) {
                int row = m0 + rl + half * 8;
                if (row >= E2) continue;
#pragma unroll
                for (int e = 0; e < 2; e++) {
                    int col = cb + e;
                    float gw = C2[mt][nt][half * 2 + e] + bgw[col];
                    float gt = C3[mt][nt][half * 2 + e] + bgt[col];
                    float sig = 1.f / (1.f + __expf(-gw));
                    out[(size_t)row * H + col] =
                        Ss[rl + half * 8][col] + sig * tanhf(gt);
                }
            }
        }
    }
}

// --------------------------------------------------------------------------
extern "C" void kernel_launch(void* const* d_in, const int* in_sizes, int n_in,
                              void* d_out, int out_size) {
    const float* t_e2 = (const float*)d_in[0];
    const float* h    = (const float*)d_in[1];
    const int*   ei1  = (const int*)d_in[2];
    const int*   ei2  = (const int*)d_in[3];
    const int*   e1e2 = (const int*)d_in[4];
    const float* rbf1 = (const float*)d_in[7];
    const float* rbf2 = (const float*)d_in[8];
    const float* sph  = (const float*)d_in[9];
    const int*   nn_p = (const int*)d_in[10];
    const float* w1   = (const float*)d_in[11];
    const float* b1   = (const float*)d_in[12];
    const float* w2   = (const float*)d_in[13];
    const float* b2   = (const float*)d_in[14];
    const float* wgw  = (const float*)d_in[15];
    const float* bgw  = (const float*)d_in[16];
    const float* wgt  = (const float*)d_in[17];
    const float* bgt  = (const float*)d_in[18];

    int E1 = in_sizes[4];
    int E2 = in_sizes[0] / H;
    const int* src1 = ei1;
    const int* dst1 = ei1 + E1;
    const int* src2 = ei2;
    const int* dst2 = ei2 + E2;

    float *pU, *pV, *pZ;
    cudaGetSymbolAddress((void**)&pU, g_U);
    cudaGetSymbolAddress((void**)&pV, g_V);
    cudaGetSymbolAddress((void**)&pZ, g_Z);

    size_t fsmem = (size_t)(2 * 64 * 132 + 2 * 32 * 132) * 4;
    cudaFuncSetAttribute(k_final, cudaFuncAttributeMaxDynamicSharedMemorySize, (int)fsmem);
    size_t uvsmem = (size_t)(2 * 64 * 36 + 4 * 32 * 132) * 4 + 4 * 64 * sizeof(int);
    cudaFuncSetAttribute(k_projUV, cudaFuncAttributeMaxDynamicSharedMemorySize, (int)uvsmem);

    static cudaStream_t s1 = nullptr, s2 = nullptr;
    static cudaEvent_t evRoot = nullptr, ev1 = nullptr, ev2 = nullptr;
    if (!s1) {
        cudaStreamCreateWithFlags(&s1, cudaStreamNonBlocking);
        cudaStreamCreateWithFlags(&s2, cudaStreamNonBlocking);
        cudaEventCreateWithFlags(&evRoot, cudaEventDisableTiming);
        cudaEventCreateWithFlags(&ev1, cudaEventDisableTiming);
        cudaEventCreateWithFlags(&ev2, cudaEventDisableTiming);
    }

    // ---- fork: projections run concurrently with wedge-list construction --
    cudaEventRecord(evRoot, 0);
    cudaStreamWaitEvent(s1, evRoot, 0);
    cudaStreamWaitEvent(s2, evRoot, 0);

    // s1: merged U+V projection (fp16 mma, starts immediately)
    k_projUV<<<(E1 + 63) / 64, 256, uvsmem, s1>>>(t_e2, h, e1e2, src1, dst1,
                                                  rbf1, E1, w1, pU, pV);
    cudaEventRecord(ev1, s1);

    // s2: Z projection
    {
        GSpec gz;
        gz.nseg = 2;
        gz.base[0] = t_e2; gz.idx[0] = nullptr; gz.pitch[0] = H;  gz.width[0] = 128; gz.wrow[0] = 256;
        gz.base[1] = rbf2; gz.idx[1] = nullptr; gz.pitch[1] = 32; gz.width[1] = 32;  gz.wrow[1] = 832;
        gz.base[2] = t_e2; gz.idx[2] = nullptr; gz.pitch[2] = H;  gz.width[2] = 0;   gz.wrow[2] = 0;
        gz.base[3] = t_e2; gz.idx[3] = nullptr; gz.pitch[3] = H;  gz.width[3] = 0;   gz.wrow[3] = 0;
        k_proj<<<(E2 + 63) / 64, NT, 0, s2>>>(gz, E2, w1, pZ);
    }
    cudaEventRecord(ev2, s2);

    // default stream: wedge-list construction chain
    k_ptr<<<(NMAX + 1 + NT - 1) / NT, NT>>>(src1, E1, nn_p);
    k_count<<<(E2 + NT - 1) / NT, NT>>>(src2, dst2, dst1, E2);
    int nscan = (E2 + 2047) / 2048;
    k_scan_part<<<nscan, NT>>>(E2);
    k_scan_top<<<1, 32>>>(nscan, E2);
    k_scan_write<<<nscan, NT>>>(E2);
    k_fill<<<(E2 + NT - 1) / NT, NT>>>(src2, dst2, dst1, E2);

    // ---- join ----
    cudaStreamWaitEvent(0, ev1, 0);
    cudaStreamWaitEvent(0, ev2, 0);

    // per-e2 hidden sum
    {
        int blocks = (E2 * 32 + NT - 1) / NT;
        k_hsum<<<blocks, NT>>>(sph, w1, b1, E2);
    }

    // final: unified pipelined 3-stage GEMM + gated output
    k_final<<<(E2 + 63) / 64, NT, fsmem>>>(t_e2, w2, b2, wgw, bgw, wgt, bgt, E2,
                                           (float*)d_out);
}

// round 14
// speedup vs baseline: 1.1266x; 1.0201x over previous
#include <cuda_runtime.h>
#include <cuda_fp16.h>

#define H     128
#define NT    256
#define NMAX  10016
#define E1MAX 80000
#define E2MAX 80000
#define WCAP  (E1MAX*16)

// ------- scratch (static device globals; no runtime allocation) ----------
__device__ int   g_ptr[NMAX + 2];
__device__ int   g_cnt[E2MAX];
__device__ int   g_part[128];
__device__ int   g_wptr[E2MAX + 1];
__device__ int   g_weik[WCAP];
__device__ int   g_wekj[WCAP];
__device__ float g_U[(size_t)E1MAX * H];
__device__ float g_V[(size_t)E1MAX * H];
__device__ float g_Z[(size_t)E2MAX * H];
__device__ float g_S[(size_t)E2MAX * H];

// ------------------------- helpers ---------------------------------------
__device__ __forceinline__ float to_tf32(float x) {
    unsigned u;
    asm("cvt.rna.tf32.f32 %0, %1;" : "=r"(u) : "f"(x));
    return __uint_as_float(u);
}

__device__ __forceinline__ void mma_tf32(float c[4], const unsigned a[4],
                                         unsigned b0, unsigned b1) {
    asm volatile(
        "mma.sync.aligned.m16n8k8.row.col.f32.tf32.tf32.f32 "
        "{%0,%1,%2,%3}, {%4,%5,%6,%7}, {%8,%9}, {%0,%1,%2,%3};"
        : "+f"(c[0]), "+f"(c[1]), "+f"(c[2]), "+f"(c[3])
        : "r"(a[0]), "r"(a[1]), "r"(a[2]), "r"(a[3]), "r"(b0), "r"(b1));
}

// fp16 mma m16n8k16: C (fp32) layout identical to m16n8k8
__device__ __forceinline__ void mma_f16(float c[4], const unsigned a[4],
                                        unsigned b0, unsigned b1) {
    asm volatile(
        "mma.sync.aligned.m16n8k16.row.col.f32.f16.f16.f32 "
        "{%0,%1,%2,%3}, {%4,%5,%6,%7}, {%8,%9}, {%0,%1,%2,%3};"
        : "+f"(c[0]), "+f"(c[1]), "+f"(c[2]), "+f"(c[3])
        : "r"(a[0]), "r"(a[1]), "r"(a[2]), "r"(a[3]), "r"(b0), "r"(b1));
}

__device__ __forceinline__ unsigned pack2(float lo, float hi) {
    __half2 h = __floats2half2_rn(lo, hi);
    return *reinterpret_cast<unsigned*>(&h);
}

__device__ __forceinline__ void cpa16(void* sdst, const void* gsrc) {
    unsigned s = (unsigned)__cvta_generic_to_shared(sdst);
    asm volatile("cp.async.cg.shared.global [%0], [%1], 16;\n" :: "r"(s), "l"(gsrc));
}
#define CP_COMMIT() asm volatile("cp.async.commit_group;\n")
#define CP_WAIT0()  asm volatile("cp.async.wait_group 0;\n")
#define CP_WAIT1()  asm volatile("cp.async.wait_group 1;\n")

// ---------------- CSR ptr: g_ptr[v] = lower_bound(src1, v) ---------------
__global__ void k_ptr(const int* __restrict__ src1, int E1, const int* __restrict__ nn_p) {
    int v = blockIdx.x * blockDim.x + threadIdx.x;
    int nn = *nn_p;
    if (v > nn || v > NMAX) return;
    int lo = 0, hi = E1;
    while (lo < hi) { int mid = (lo + hi) >> 1; if (src1[mid] < v) lo = mid + 1; else hi = mid; }
    g_ptr[v] = lo;
}

// ------------- per-e2-edge wedge count (sorted-by-eij build) --------------
__global__ void k_count(const int* __restrict__ src2, const int* __restrict__ dst2,
                        const int* __restrict__ dst1, int E2) {
    int q = blockIdx.x * blockDim.x + threadIdx.x;
    if (q >= E2) return;
    int i = src2[q], j = dst2[q];
    int c = 0;
    if (i != j) {
        int b0 = g_ptr[i], e0 = g_ptr[i + 1];
        for (int t = b0; t < e0; t++) {
            int k = dst1[t];
            if (k == i || k == j) continue;
            int b1 = g_ptr[k], e1 = g_ptr[k + 1];
            for (int u = b1; u < e1; u++)
                if (dst1[u] == j) c++;
        }
    }
    g_cnt[q] = c;
}

// ----------------------- 3-phase exclusive scan ---------------------------
__global__ void k_scan_part(int n) {
    int blk = blockIdx.x, tid = threadIdx.x, lane = tid & 31, wid = tid >> 5;
    int base = blk * 2048 + tid * 8;
    int s = 0;
#pragma unroll
    for (int i = 0; i < 8; i++) { int idx = base + i; if (idx < n) s += g_cnt[idx]; }
#pragma unroll
    for (int off = 16; off > 0; off >>= 1) s += __shfl_down_sync(0xffffffffu, s, off);
    __shared__ int red[8];
    if (lane == 0) red[wid] = s;
    __syncthreads();
    if (tid == 0) {
        int tot = 0;
#pragma unroll
        for (int w = 0; w < 8; w++) tot += red[w];
        g_part[blk] = tot;
    }
}
__global__ void k_scan_top(int nb, int n) {
    if (threadIdx.x == 0) {
        int acc = 0;
        for (int b = 0; b < nb; b++) { int v = g_part[b]; g_part[b] = acc; acc += v; }
        g_wptr[n] = acc;
    }
}
__global__ void k_scan_write(int n) {
    int blk = blockIdx.x, tid = threadIdx.x, lane = tid & 31, wid = tid >> 5;
    int base = blk * 2048 + tid * 8;
    int v[8]; int s = 0;
#pragma unroll
    for (int i = 0; i < 8; i++) {
        int idx = base + i;
        v[i] = (idx < n) ? g_cnt[idx] : 0;
        s += v[i];
    }
    int x = s;
#pragma unroll
    for (int off = 1; off < 32; off <<= 1) {
        int t = __shfl_up_sync(0xffffffffu, x, off);
        if (lane >= off) x += t;
    }
    __shared__ int wsum[8];
    if (lane == 31) wsum[wid] = x;
    __syncthreads();
    __shared__ int wexc[8];
    if (tid == 0) {
        int acc = 0;
#pragma unroll
        for (int w = 0; w < 8; w++) { wexc[w] = acc; acc += wsum[w]; }
    }
    __syncthreads();
    int run = g_part[blk] + wexc[wid] + x - s;
#pragma unroll
    for (int i = 0; i < 8; i++) {
        int idx = base + i;
        if (idx < n) g_wptr[idx] = run;
        run += v[i];
    }
}

__global__ void k_fill(const int* __restrict__ src2, const int* __restrict__ dst2,
                       const int* __restrict__ dst1, int E2) {
    int q = blockIdx.x * blockDim.x + threadIdx.x;
    if (q >= E2) return;
    int i = src2[q], j = dst2[q];
    if (i == j) return;
    int pos = g_wptr[q];
    int b0 = g_ptr[i], e0 = g_ptr[i + 1];
    for (int t = b0; t < e0; t++) {
        int k = dst1[t];
        if (k == i || k == j) continue;
        int b1 = g_ptr[k], e1 = g_ptr[k + 1];
        for (int u = b1; u < e1; u++)
            if (dst1[u] == j) {
                if (pos < WCAP) { g_weik[pos] = t; g_wekj[pos] = u; }
                pos++;
            }
    }
}

// ---------- merged U+V projection (M=64, occ 2, cp.async, fp16 mma) -------
__global__ void __launch_bounds__(256, 2) k_projUV(
    const float* __restrict__ t_e2, const float* __restrict__ h,
    const int* __restrict__ e1e2, const int* __restrict__ src1,
    const int* __restrict__ dst1, const float* __restrict__ rbf1,
    int E1, const float* __restrict__ W,
    float* __restrict__ outU, float* __restrict__ outV) {
    extern __shared__ float sm[];
    float(*As)[64][36]  = (float(*)[64][36])sm;                    // 2 stages
    float(*BU)[32][132] = (float(*)[32][132])(sm + 2 * 64 * 36);
    float(*BV)[32][132] = (float(*)[32][132])(sm + 2 * 64 * 36 + 2 * 32 * 132);
    int* s_row = (int*)(sm + 2 * 64 * 36 + 4 * 32 * 132);          // [4][64]

    int tid = threadIdx.x, lane = tid & 31, wid = tid >> 5;
    int group = wid >> 2;            // 0 = U, 1 = V
    int warp_m = wid & 1;            // 2 row groups of 32
    int warp_n = (wid >> 1) & 1;     // 2 col groups of 64
    int m0 = blockIdx.x * 64;

    for (int r = tid; r < 64; r += 256) {
        int row = m0 + r;
        int rc = (row < E1) ? row : 0;
        s_row[0 * 64 + r] = (row < E1) ? e1e2[row] : 0;
        s_row[1 * 64 + r] = (row < E1) ? src1[row] : 0;
        s_row[2 * 64 + r] = (row < E1) ? dst1[row] : 0;
        s_row[3 * 64 + r] = rc;
    }
    __syncthreads();

    const int wrowU[4] = {0, 384, 512, 768};
    const int wrowV[4] = {128, 0, 640, 800};

    auto copy_chunk = [&](int kc, int st) {
        int seg = kc >> 2;
        int off = (kc & 3) * 32;
        const float* base; int pitch;
        if (seg == 0)      { base = t_e2; pitch = H; }
        else if (seg == 1) { base = h;    pitch = H; }
        else if (seg == 2) { base = h;    pitch = H; }
        else               { base = rbf1; pitch = 32; }
#pragma unroll
        for (int it = 0; it < 2; it++) {
            int pos = tid + it * 256;
            int r = pos >> 3, c4 = pos & 7;
            const float* src = base + (size_t)s_row[seg * 64 + r] * pitch + off + c4 * 4;
            cpa16(&As[st][r][c4 * 4], src);
        }
        const float* WU = W + (size_t)(wrowU[seg] + off) * H;
#pragma unroll
        for (int it = 0; it < 4; it++) {
            int pos = tid + it * 256;
            int r = pos >> 5, c4 = pos & 31;
            cpa16(&BU[st][r][c4 * 4], WU + r * H + c4 * 4);
        }
        if (seg != 1) {
            const float* WV = W + (size_t)(wrowV[seg] + off) * H;
#pragma unroll
            for (int it = 0; it < 4; it++) {
                int pos = tid + it * 256;
                int r = pos >> 5, c4 = pos & 31;
                cpa16(&BV[st][r][c4 * 4], WV + r * H + c4 * 4);
            }
        }
    };

    float C[2][8][4] = {};
    const int TOT = 13;

    copy_chunk(0, 0);
    CP_COMMIT();
    for (int kc = 0; kc < TOT; kc++) {
        if (kc + 1 < TOT) { copy_chunk(kc + 1, (kc + 1) & 1); CP_COMMIT(); CP_WAIT1(); }
        else              { CP_WAIT0(); }
        __syncthreads();
        int st = kc & 1;
        int seg = kc >> 2;
        if (group == 0 || seg != 1) {
            float(*Bsrc)[132] = group ? BV[st] : BU[st];
            int c2 = (lane & 3) * 2;
#pragma unroll
            for (int ks2 = 0; ks2 < 2; ks2++) {
                int kb = ks2 * 16;
                unsigned a[2][4];
#pragma unroll
                for (int mt = 0; mt < 2; mt++) {
                    int rb = warp_m * 32 + mt * 16 + (lane >> 2);
                    a[mt][0] = pack2(As[st][rb][kb + c2],         As[st][rb][kb + c2 + 1]);
                    a[mt][1] = pack2(As[st][rb + 8][kb + c2],     As[st][rb + 8][kb + c2 + 1]);
                    a[mt][2] = pack2(As[st][rb][kb + c2 + 8],     As[st][rb][kb + c2 + 9]);
                    a[mt][3] = pack2(As[st][rb + 8][kb + c2 + 8], As[st][rb + 8][kb + c2 + 9]);
                }
#pragma unroll
                for (int nt = 0; nt < 8; nt++) {
                    int nb = warp_n * 64 + nt * 8 + (lane >> 2);
                    unsigned b0 = pack2(Bsrc[kb + c2][nb],     Bsrc[kb + c2 + 1][nb]);
                    unsigned b1 = pack2(Bsrc[kb + c2 + 8][nb], Bsrc[kb + c2 + 9][nb]);
                    mma_f16(C[0][nt], a[0], b0, b1);
                    mma_f16(C[1][nt], a[1], b0, b1);
                }
            }
        }
        __syncthreads();
    }

    float* outp = group ? outV : outU;
#pragma unroll
    for (int mt = 0; mt < 2; mt++) {
        int r0 = m0 + warp_m * 32 + mt * 16 + (lane >> 2);
#pragma unroll
        for (int nt = 0; nt < 8; nt++) {
            int cb = warp_n * 64 + nt * 8 + 2 * (lane & 3);
            if (r0 < E1)
                *(float2*)&outp[(size_t)r0 * H + cb] =
                    make_float2(C[mt][nt][0], C[mt][nt][1]);
            if (r0 + 8 < E1)
                *(float2*)&outp[(size_t)(r0 + 8) * H + cb] =
                    make_float2(C[mt][nt][2], C[mt][nt][3]);
        }
    }
}

// -------------- generic gathered GEMM (used for Z) ------------------------
struct GSpec {
    const float* base[4];
    const int*   idx[4];
    int          pitch[4];
    int          width[4];
    int          wrow[4];
    int          nseg;
};

__global__ void __launch_bounds__(NT) k_proj(GSpec g, int R, const float* __restrict__ W,
                                             float* __restrict__ out) {
    __shared__ float As[64][33];
    __shared__ float Bs[32][132];
    __shared__ int   s_row[4][64];
    int tid = threadIdx.x, lane = tid & 31, wid = tid >> 5;
    int warp_m = wid & 1, warp_n = wid >> 1;
    int m0 = blockIdx.x * 64;

    for (int s = 0; s < g.nseg; s++)
        for (int r = tid; r < 64; r += NT) {
            int row = m0 + r;
            s_row[s][r] = (row < R) ? (g.idx[s] ? g.idx[s][row] : row) : 0;
        }
    __syncthreads();

    float C[2][4][4] = {};
    int tot = 0;
    for (int s = 0; s < g.nseg; s++) tot += g.width[s] >> 5;

    int seg = 0, segch = 0;
    for (int kc = 0; kc < tot; kc++) {
        int off = segch * 32;
        const float* base = g.base[seg];
        int pitch = g.pitch[seg];
        const float* Wc = W + (size_t)(g.wrow[seg] + off) * H;
#pragma unroll
        for (int it = 0; it < 8; it++) {
            int pos = tid + it * NT;
            int r = pos >> 5, c = pos & 31;
            As[r][c] = to_tf32(base[(size_t)s_row[seg][r] * pitch + off + c]);
        }
#pragma unroll
        for (int it = 0; it < 16; it++) {
            int pos = tid + it * NT;
            int r = pos >> 7, c = pos & 127;
            Bs[r][c] = to_tf32(Wc[pos]);
        }
        __syncthreads();
#pragma unroll
        for (int ks = 0; ks < 4; ks++) {
            int k0 = ks * 8;
            unsigned a[2][4];
#pragma unroll
            for (int mt = 0; mt < 2; mt++) {
                int rb = warp_m * 32 + mt * 16 + (lane >> 2);
                int cb = k0 + (lane & 3);
                a[mt][0] = __float_as_uint(As[rb][cb]);
                a[mt][1] = __float_as_uint(As[rb + 8][cb]);
                a[mt][2] = __float_as_uint(As[rb][cb + 4]);
                a[mt][3] = __float_as_uint(As[rb + 8][cb + 4]);
            }
#pragma unroll
            for (int nt = 0; nt < 4; nt++) {
                int nb = warp_n * 32 + nt * 8 + (lane >> 2);
                unsigned b0 = __float_as_uint(Bs[k0 + (lane & 3)][nb]);
                unsigned b1 = __float_as_uint(Bs[k0 + (lane & 3) + 4][nb]);
                mma_tf32(C[0][nt], a[0], b0, b1);
                mma_tf32(C[1][nt], a[1], b0, b1);
            }
        }
        __syncthreads();
        segch++;
        if ((segch << 5) >= g.width[seg]) { seg++; segch = 0; }
    }

#pragma unroll
    for (int mt = 0; mt < 2; mt++) {
        int r0 = warp_m * 32 + mt * 16 + (lane >> 2);
#pragma unroll
        for (int nt = 0; nt < 4; nt++) {
            int cb = warp_n * 32 + nt * 8 + 2 * (lane & 3);
            int row = m0 + r0;
            if (row < R)
                *(float2*)&out[(size_t)row * H + cb] = make_float2(C[mt][nt][0], C[mt][nt][1]);
            if (row + 8 < R)
                *(float2*)&out[(size_t)(row + 8) * H + cb] = make_float2(C[mt][nt][2], C[mt][nt][3]);
        }
    }
}

// ---- per-e2 hidden sum: S[q] = sum_w silu(U[eik]+V[ekj]+Z[q]+c*w864+b1) ---
__global__ void __launch_bounds__(NT) k_hsum(const float* __restrict__ sph,
                                             const float* __restrict__ w1,
                                             const float* __restrict__ b1, int E2) {
    int warp = (blockIdx.x * blockDim.x + threadIdx.x) >> 5;
    int lane = threadIdx.x & 31;
    if (warp >= E2) return;
    int q = warp;
    int beg = g_wptr[q], end = g_wptr[q + 1];
    if (beg > WCAP) beg = WCAP;
    if (end > WCAP) end = WCAP;
    float4 z  = *(const float4*)&g_Z[(size_t)q * H + lane * 4];
    float4 w8 = *(const float4*)&w1[(size_t)864 * H + lane * 4];
    float4 bb = *(const float4*)&b1[lane * 4];
    float4 acc = make_float4(0.f, 0.f, 0.f, 0.f);

    float4 u, v; float cf = 0.f;
    int w = beg;
    if (w < end) {
        int a = g_weik[w], b = g_wekj[w];
        cf = __ldg(&sph[a * 3 + 1]) * __ldg(&sph[b * 3 + 1]);
        u = *(const float4*)&g_U[(size_t)a * H + lane * 4];
        v = *(const float4*)&g_V[(size_t)b * H + lane * 4];
    }
    while (w < end) {
        float4 cu = u, cv = v; float c0 = cf;
        int nw = w + 1;
        if (nw < end) {
            int a = g_weik[nw], b = g_wekj[nw];
            cf = __ldg(&sph[a * 3 + 1]) * __ldg(&sph[b * 3 + 1]);
            u = *(const float4*)&g_U[(size_t)a * H + lane * 4];
            v = *(const float4*)&g_V[(size_t)b * H + lane * 4];
        }
        float x;
        x = cu.x + cv.x + z.x + c0 * w8.x + bb.x; acc.x += x / (1.f + __expf(-x));
        x = cu.y + cv.y + z.y + c0 * w8.y + bb.y; acc.y += x / (1.f + __expf(-x));
        x = cu.z + cv.z + z.z + c0 * w8.z + bb.z; acc.z += x / (1.f + __expf(-x));
        x = cu.w + cv.w + z.w + c0 * w8.w + bb.w; acc.w += x / (1.f + __expf(-x));
        w = nw;
    }
    *(float4*)&g_S[(size_t)q * H + lane * 4] = acc;
}

// ---- final (unified 12-chunk cp.async pipeline, fp16 mma):
//  chunks 0-3:  C  = S @ W2      (A = Ss)
//  chunks 4-7:  C2 = m @ wgw     (A = Ms, written at kc==3; Ss reloaded w/ t)
//  chunks 8-11: C3 = t @ wgt     (A = Ss)
//  out = t + sigmoid(C2+bgw) * tanh(C3+bgt)
__global__ void __launch_bounds__(NT) k_final(const float* __restrict__ t_e2,
                                              const float* __restrict__ w2,
                                              const float* __restrict__ b2,
                                              const float* __restrict__ wgw,
                                              const float* __restrict__ bgw,
                                              const float* __restrict__ wgt,
                                              const float* __restrict__ bgt,
                                              int E2, float* __restrict__ out) {
    extern __shared__ float sm[];
    float(*Ss)[132] = (float(*)[132])sm;                           // 64 x 132
    float(*Ms)[132] = (float(*)[132])(sm + 64 * 132);              // 64 x 132
    float(*Bs)[32][132] = (float(*)[32][132])(sm + 2 * 64 * 132);  // 2 stages
    __shared__ int s_cnt[64];

    int tid = threadIdx.x, lane = tid & 31, wid = tid >> 5;
    int warp_m = wid & 1, warp_n = wid >> 1;
    int m0 = blockIdx.x * 64;

    for (int r = tid; r < 64; r += NT) {
        int row = m0 + r;
        s_cnt[r] = (row < E2) ? (g_wptr[row + 1] - g_wptr[row]) : 0;
    }
#pragma unroll
    for (int it = 0; it < 8; it++) {
        int pos = tid + it * NT;
        int r = pos >> 5, c4 = pos & 31;
        int row = m0 + r;
        float4 v = (row < E2) ? *(const float4*)&g_S[(size_t)row * H + c4 * 4]
                              : make_float4(0.f, 0.f, 0.f, 0.f);
        *(float4*)&Ss[r][c4 * 4] = v;
    }

    auto loadB = [&](int kc, int st) {
        const float* Wc;
        if (kc < 4)      Wc = w2  + (size_t)kc * 32 * H;
        else if (kc < 8) Wc = wgw + (size_t)(kc - 4) * 32 * H;
        else             Wc = wgt + (size_t)(kc - 8) * 32 * H;
#pragma unroll
        for (int it = 0; it < 4; it++) {
            int pos = tid + it * NT;
            int r = pos >> 5, c4 = pos & 31;
            cpa16(&Bs[st][r][c4 * 4], Wc + r * H + c4 * 4);
        }
    };

    float C[2][4][4] = {};
    float C2[2][4][4] = {};
    float C3[2][4][4] = {};
    loadB(0, 0);
    CP_COMMIT();
    __syncthreads();
    for (int kc = 0; kc < 12; kc++) {
        if (kc + 1 < 12) { loadB(kc + 1, (kc + 1) & 1); CP_COMMIT(); CP_WAIT1(); }
        else             { CP_WAIT0(); }
        __syncthreads();
        int st = kc & 1;
        int stage = kc >> 2;
        int kcol = (kc & 3) * 32;
        float(*Asrc)[132] = (stage == 1) ? Ms : Ss;
        int c2 = (lane & 3) * 2;
#pragma unroll
        for (int ks2 = 0; ks2 < 2; ks2++) {
            int ka = kcol + ks2 * 16;   // A column base
            int kb = ks2 * 16;          // B row base within chunk
            unsigned a[2][4];
#pragma unroll
            for (int mt = 0; mt < 2; mt++) {
                int rb = warp_m * 32 + mt * 16 + (lane >> 2);
                a[mt][0] = pack2(Asrc[rb][ka + c2],         Asrc[rb][ka + c2 + 1]);
                a[mt][1] = pack2(Asrc[rb + 8][ka + c2],     Asrc[rb + 8][ka + c2 + 1]);
                a[mt][2] = pack2(Asrc[rb][ka + c2 + 8],     Asrc[rb][ka + c2 + 9]);
                a[mt][3] = pack2(Asrc[rb + 8][ka + c2 + 8], Asrc[rb + 8][ka + c2 + 9]);
            }
#pragma unroll
            for (int nt = 0; nt < 4; nt++) {
                int nb = warp_n * 32 + nt * 8 + (lane >> 2);
                unsigned b0 = pack2(Bs[st][kb + c2][nb],     Bs[st][kb + c2 + 1][nb]);
                unsigned b1 = pack2(Bs[st][kb + c2 + 8][nb], Bs[st][kb + c2 + 9][nb]);
                if (stage == 0)      { mma_f16(C[0][nt],  a[0], b0, b1); mma_f16(C[1][nt],  a[1], b0, b1); }
                else if (stage == 1) { mma_f16(C2[0][nt], a[0], b0, b1); mma_f16(C2[1][nt], a[1], b0, b1); }
                else                 { mma_f16(C3[0][nt], a[0], b0, b1); mma_f16(C3[1][nt], a[1], b0, b1); }
            }
        }
        __syncthreads();
        if (kc == 3) {
#pragma unroll
            for (int mt = 0; mt < 2; mt++) {
                int r0 = warp_m * 32 + mt * 16 + (lane >> 2);
                float cn0 = (float)s_cnt[r0], cn1 = (float)s_cnt[r0 + 8];
#pragma unroll
                for (int nt = 0; nt < 4; nt++) {
                    int cb = warp_n * 32 + nt * 8 + 2 * (lane & 3);
                    Ms[r0][cb]         = C[mt][nt][0] + cn0 * b2[cb];
                    Ms[r0][cb + 1]     = C[mt][nt][1] + cn0 * b2[cb + 1];
                    Ms[r0 + 8][cb]     = C[mt][nt][2] + cn1 * b2[cb];
                    Ms[r0 + 8][cb + 1] = C[mt][nt][3] + cn1 * b2[cb + 1];
                }
            }
#pragma unroll
            for (int it = 0; it < 8; it++) {
                int pos = tid + it * NT;
                int r = pos >> 5, c4 = pos & 31;
                int row = m0 + r;
                float4 v = (row < E2) ? *(const float4*)&t_e2[(size_t)row * H + c4 * 4]
                                      : make_float4(0.f, 0.f, 0.f, 0.f);
                *(float4*)&Ss[r][c4 * 4] = v;
            }
            __syncthreads();
        }
    }

#pragma unroll
    for (int mt = 0; mt < 2; mt++) {
        int rl = warp_m * 32 + mt * 16 + (lane >> 2);
#pragma unroll
        for (int nt = 0; nt < 4; nt++) {
            int cb = warp_n * 32 + nt * 8 + 2 * (lane & 3);
#pragma unroll
            for (int half = 0; half < 2; half++) {
                int row = m0 + rl + half * 8;
                if (row >= E2) continue;
#pragma unroll
                for (int e = 0; e < 2; e++) {
                    int col = cb + e;
                    float gw = C2[mt][nt][half * 2 + e] + bgw[col];
                    float gt = C3[mt][nt][half * 2 + e] + bgt[col];
                    float sig = 1.f / (1.f + __expf(-gw));
                    out[(size_t)row * H + col] =
                        Ss[rl + half * 8][col] + sig * tanhf(gt);
                }
            }
        }
    }
}

// --------------------------------------------------------------------------
extern "C" void kernel_launch(void* const* d_in, const int* in_sizes, int n_in,
                              void* d_out, int out_size) {
    const float* t_e2 = (const float*)d_in[0];
    const float* h    = (const float*)d_in[1];
    const int*   ei1  = (const int*)d_in[2];
    const int*   ei2  = (const int*)d_in[3];
    const int*   e1e2 = (const int*)d_in[4];
    const float* rbf1 = (const float*)d_in[7];
    const float* rbf2 = (const float*)d_in[8];
    const float* sph  = (const float*)d_in[9];
    const int*   nn_p = (const int*)d_in[10];
    const float* w1   = (const float*)d_in[11];
    const float* b1   = (const float*)d_in[12];
    const float* w2   = (const float*)d_in[13];
    const float* b2   = (const float*)d_in[14];
    const float* wgw  = (const float*)d_in[15];
    const float* bgw  = (const float*)d_in[16];
    const float* wgt  = (const float*)d_in[17];
    const float* bgt  = (const float*)d_in[18];

    int E1 = in_sizes[4];
    int E2 = in_sizes[0] / H;
    const int* src1 = ei1;
    const int* dst1 = ei1 + E1;
    const int* src2 = ei2;
    const int* dst2 = ei2 + E2;

    float *pU, *pV, *pZ;
    cudaGetSymbolAddress((void**)&pU, g_U);
    cudaGetSymbolAddress((void**)&pV, g_V);
    cudaGetSymbolAddress((void**)&pZ, g_Z);

    size_t fsmem = (size_t)(2 * 64 * 132 + 2 * 32 * 132) * 4;
    cudaFuncSetAttribute(k_final, cudaFuncAttributeMaxDynamicSharedMemorySize, (int)fsmem);
    size_t uvsmem = (size_t)(2 * 64 * 36 + 4 * 32 * 132) * 4 + 4 * 64 * sizeof(int);
    cudaFuncSetAttribute(k_projUV, cudaFuncAttributeMaxDynamicSharedMemorySize, (int)uvsmem);

    static cudaStream_t s1 = nullptr, s2 = nullptr;
    static cudaEvent_t evRoot = nullptr, ev1 = nullptr, ev2 = nullptr;
    if (!s1) {
        cudaStreamCreateWithFlags(&s1, cudaStreamNonBlocking);
        cudaStreamCreateWithFlags(&s2, cudaStreamNonBlocking);
        cudaEventCreateWithFlags(&evRoot, cudaEventDisableTiming);
        cudaEventCreateWithFlags(&ev1, cudaEventDisableTiming);
        cudaEventCreateWithFlags(&ev2, cudaEventDisableTiming);
    }

    // ---- fork: projections run concurrently with wedge-list construction --
    cudaEventRecord(evRoot, 0);
    cudaStreamWaitEvent(s1, evRoot, 0);
    cudaStreamWaitEvent(s2, evRoot, 0);

    // s1: merged U+V projection (fp16 mma, starts immediately)
    k_projUV<<<(E1 + 63) / 64, 256, uvsmem, s1>>>(t_e2, h, e1e2, src1, dst1,
                                                  rbf1, E1, w1, pU, pV);
    cudaEventRecord(ev1, s1);

    // s2: Z projection
    {
        GSpec gz;
        gz.nseg = 2;
        gz.base[0] = t_e2; gz.idx[0] = nullptr; gz.pitch[0] = H;  gz.width[0] = 128; gz.wrow[0] = 256;
        gz.base[1] = rbf2; gz.idx[1] = nullptr; gz.pitch[1] = 32; gz.width[1] = 32;  gz.wrow[1] = 832;
        gz.base[2] = t_e2; gz.idx[2] = nullptr; gz.pitch[2] = H;  gz.width[2] = 0;   gz.wrow[2] = 0;
        gz.base[3] = t_e2; gz.idx[3] = nullptr; gz.pitch[3] = H;  gz.width[3] = 0;   gz.wrow[3] = 0;
        k_proj<<<(E2 + 63) / 64, NT, 0, s2>>>(gz, E2, w1, pZ);
    }
    cudaEventRecord(ev2, s2);

    // default stream: wedge-list construction chain
    k_ptr<<<(NMAX + 1 + NT - 1) / NT, NT>>>(src1, E1, nn_p);
    k_count<<<(E2 + NT - 1) / NT, NT>>>(src2, dst2, dst1, E2);
    int nscan = (E2 + 2047) / 2048;
    k_scan_part<<<nscan, NT>>>(E2);
    k_scan_top<<<1, 32>>>(nscan, E2);
    k_scan_write<<<nscan, NT>>>(E2);
    k_fill<<<(E2 + NT - 1) / NT, NT>>>(src2, dst2, dst1, E2);

    // ---- join ----
    cudaStreamWaitEvent(0, ev1, 0);
    cudaStreamWaitEvent(0, ev2, 0);

    // per-e2 hidden sum
    {
        int blocks = (E2 * 32 + NT - 1) / NT;
        k_hsum<<<blocks, NT>>>(sph, w1, b1, E2);
    }

    // final: unified pipelined 3-stage GEMM (fp16 mma) + gated output
    k_final<<<(E2 + 63) / 64, NT, fsmem>>>(t_e2, w2, b2, wgw, bgw, wgt, bgt, E2,
                                           (float*)d_out);
}

// round 15
// speedup vs baseline: 1.2064x; 1.0708x over previous
#include <cuda_runtime.h>
#include <cuda_fp16.h>

#define H     128
#define NT    256
#define NMAX  10016
#define E1MAX 80000
#define E2MAX 80000
#define WCAP  (E1MAX*16)
#define WTP   872   // padded k-pitch of transposed half W1

// ------- scratch (static device globals; no runtime allocation) ----------
__device__ int    g_ptr[NMAX + 2];
__device__ int    g_cnt[E2MAX];
__device__ int    g_part[128];
__device__ int    g_wptr[E2MAX + 1];
__device__ int    g_weik[WCAP];
__device__ int    g_wekj[WCAP];
__device__ float  g_U[(size_t)E1MAX * H];
__device__ float  g_V[(size_t)E1MAX * H];
__device__ float  g_Z[(size_t)E2MAX * H];
__device__ float  g_S[(size_t)E2MAX * H];
__device__ __half g_tH[(size_t)E2MAX * H];
__device__ __half g_hH[(size_t)NMAX * H];
__device__ __half g_rH[(size_t)E1MAX * 32];
__device__ __half g_WtH[(size_t)H * WTP];

// ------------------------- helpers ---------------------------------------
__device__ __forceinline__ float to_tf32(float x) {
    unsigned u;
    asm("cvt.rna.tf32.f32 %0, %1;" : "=r"(u) : "f"(x));
    return __uint_as_float(u);
}

__device__ __forceinline__ void mma_tf32(float c[4], const unsigned a[4],
                                         unsigned b0, unsigned b1) {
    asm volatile(
        "mma.sync.aligned.m16n8k8.row.col.f32.tf32.tf32.f32 "
        "{%0,%1,%2,%3}, {%4,%5,%6,%7}, {%8,%9}, {%0,%1,%2,%3};"
        : "+f"(c[0]), "+f"(c[1]), "+f"(c[2]), "+f"(c[3])
        : "r"(a[0]), "r"(a[1]), "r"(a[2]), "r"(a[3]), "r"(b0), "r"(b1));
}

__device__ __forceinline__ void mma_f16(float c[4], const unsigned a[4],
                                        unsigned b0, unsigned b1) {
    asm volatile(
        "mma.sync.aligned.m16n8k16.row.col.f32.f16.f16.f32 "
        "{%0,%1,%2,%3}, {%4,%5,%6,%7}, {%8,%9}, {%0,%1,%2,%3};"
        : "+f"(c[0]), "+f"(c[1]), "+f"(c[2]), "+f"(c[3])
        : "r"(a[0]), "r"(a[1]), "r"(a[2]), "r"(a[3]), "r"(b0), "r"(b1));
}

__device__ __forceinline__ unsigned pack2(float lo, float hi) {
    __half2 h = __floats2half2_rn(lo, hi);
    return *reinterpret_cast<unsigned*>(&h);
}

__device__ __forceinline__ void cpa16(void* sdst, const void* gsrc) {
    unsigned s = (unsigned)__cvta_generic_to_shared(sdst);
    asm volatile("cp.async.cg.shared.global [%0], [%1], 16;\n" :: "r"(s), "l"(gsrc));
}
#define CP_COMMIT() asm volatile("cp.async.commit_group;\n")
#define CP_WAIT0()  asm volatile("cp.async.wait_group 0;\n")
#define CP_WAIT1()  asm volatile("cp.async.wait_group 1;\n")

// ---------------- fp16 pre-conversion kernels -----------------------------
__global__ void k_cvtA(const float* __restrict__ src, __half* __restrict__ dst, int n2) {
    int i = blockIdx.x * blockDim.x + threadIdx.x;
    if (i < n2) {
        float2 v = ((const float2*)src)[i];
        ((__half2*)dst)[i] = __floats2half2_rn(v.x, v.y);
    }
}
__global__ void k_cvtW(const float* __restrict__ W) {
    int idx = blockIdx.x * blockDim.x + threadIdx.x;
    if (idx < 865 * H) {
        int k = idx >> 7, n = idx & 127;
        g_WtH[(size_t)n * WTP + k] = __float2half(W[idx]);
    }
}

// ---------------- CSR ptr: g_ptr[v] = lower_bound(src1, v) ---------------
__global__ void k_ptr(const int* __restrict__ src1, int E1, const int* __restrict__ nn_p) {
    int v = blockIdx.x * blockDim.x + threadIdx.x;
    int nn = *nn_p;
    if (v > nn || v > NMAX) return;
    int lo = 0, hi = E1;
    while (lo < hi) { int mid = (lo + hi) >> 1; if (src1[mid] < v) lo = mid + 1; else hi = mid; }
    g_ptr[v] = lo;
}

// ------------- per-e2-edge wedge count (sorted-by-eij build) --------------
__global__ void k_count(const int* __restrict__ src2, const int* __restrict__ dst2,
                        const int* __restrict__ dst1, int E2) {
    int q = blockIdx.x * blockDim.x + threadIdx.x;
    if (q >= E2) return;
    int i = src2[q], j = dst2[q];
    int c = 0;
    if (i != j) {
        int b0 = g_ptr[i], e0 = g_ptr[i + 1];
        for (int t = b0; t < e0; t++) {
            int k = dst1[t];
            if (k == i || k == j) continue;
            int b1 = g_ptr[k], e1 = g_ptr[k + 1];
            for (int u = b1; u < e1; u++)
                if (dst1[u] == j) c++;
        }
    }
    g_cnt[q] = c;
}

// ----------------------- 3-phase exclusive scan ---------------------------
__global__ void k_scan_part(int n) {
    int blk = blockIdx.x, tid = threadIdx.x, lane = tid & 31, wid = tid >> 5;
    int base = blk * 2048 + tid * 8;
    int s = 0;
#pragma unroll
    for (int i = 0; i < 8; i++) { int idx = base + i; if (idx < n) s += g_cnt[idx]; }
#pragma unroll
    for (int off = 16; off > 0; off >>= 1) s += __shfl_down_sync(0xffffffffu, s, off);
    __shared__ int red[8];
    if (lane == 0) red[wid] = s;
    __syncthreads();
    if (tid == 0) {
        int tot = 0;
#pragma unroll
        for (int w = 0; w < 8; w++) tot += red[w];
        g_part[blk] = tot;
    }
}
__global__ void k_scan_top(int nb, int n) {
    if (threadIdx.x == 0) {
        int acc = 0;
        for (int b = 0; b < nb; b++) { int v = g_part[b]; g_part[b] = acc; acc += v; }
        g_wptr[n] = acc;
    }
}
__global__ void k_scan_write(int n) {
    int blk = blockIdx.x, tid = threadIdx.x, lane = tid & 31, wid = tid >> 5;
    int base = blk * 2048 + tid * 8;
    int v[8]; int s = 0;
#pragma unroll
    for (int i = 0; i < 8; i++) {
        int idx = base + i;
        v[i] = (idx < n) ? g_cnt[idx] : 0;
        s += v[i];
    }
    int x = s;
#pragma unroll
    for (int off = 1; off < 32; off <<= 1) {
        int t = __shfl_up_sync(0xffffffffu, x, off);
        if (lane >= off) x += t;
    }
    __shared__ int wsum[8];
    if (lane == 31) wsum[wid] = x;
    __syncthreads();
    __shared__ int wexc[8];
    if (tid == 0) {
        int acc = 0;
#pragma unroll
        for (int w = 0; w < 8; w++) { wexc[w] = acc; acc += wsum[w]; }
    }
    __syncthreads();
    int run = g_part[blk] + wexc[wid] + x - s;
#pragma unroll
    for (int i = 0; i < 8; i++) {
        int idx = base + i;
        if (idx < n) g_wptr[idx] = run;
        run += v[i];
    }
}

__global__ void k_fill(const int* __restrict__ src2, const int* __restrict__ dst2,
                       const int* __restrict__ dst1, int E2) {
    int q = blockIdx.x * blockDim.x + threadIdx.x;
    if (q >= E2) return;
    int i = src2[q], j = dst2[q];
    if (i == j) return;
    int pos = g_wptr[q];
    int b0 = g_ptr[i], e0 = g_ptr[i + 1];
    for (int t = b0; t < e0; t++) {
        int k = dst1[t];
        if (k == i || k == j) continue;
        int b1 = g_ptr[k], e1 = g_ptr[k + 1];
        for (int u = b1; u < e1; u++)
            if (dst1[u] == j) {
                if (pos < WCAP) { g_weik[pos] = t; g_wekj[pos] = u; }
                pos++;
            }
    }
}

// ---------- merged U+V projection: pure-fp16 smem, no in-loop cvt ---------
// A tiles from g_tH/g_hH/g_rH (K-major half); B tiles from g_WtH (N-major,
// k-contiguous) so every fragment element is one 32-bit LDS of a half2 pair.
__global__ void __launch_bounds__(256, 2) k_projUV(
    const int* __restrict__ e1e2, const int* __restrict__ src1,
    const int* __restrict__ dst1,
    int E1, float* __restrict__ outU, float* __restrict__ outV) {
    extern __shared__ __half smh[];
    __half(*As)[64][40]  = (__half(*)[64][40])smh;                    // 2 stages
    __half(*BU)[128][40] = (__half(*)[128][40])(smh + 2 * 64 * 40);
    __half(*BV)[128][40] = (__half(*)[128][40])(smh + 2 * 64 * 40 + 2 * 128 * 40);
    int* s_row = (int*)(smh + 2 * 64 * 40 + 4 * 128 * 40);            // [4][64]

    int tid = threadIdx.x, lane = tid & 31, wid = tid >> 5;
    int group = wid >> 2;            // 0 = U, 1 = V
    int warp_m = wid & 1;            // 2 row groups of 32
    int warp_n = (wid >> 1) & 1;     // 2 col groups of 64
    int m0 = blockIdx.x * 64;

    for (int r = tid; r < 64; r += 256) {
        int row = m0 + r;
        int rc = (row < E1) ? row : 0;
        s_row[0 * 64 + r] = (row < E1) ? e1e2[row] : 0;
        s_row[1 * 64 + r] = (row < E1) ? src1[row] : 0;
        s_row[2 * 64 + r] = (row < E1) ? dst1[row] : 0;
        s_row[3 * 64 + r] = rc;
    }
    __syncthreads();

    const int wrowU[4] = {0, 384, 512, 768};
    const int wrowV[4] = {128, 0, 640, 800};

    auto copy_chunk = [&](int kc, int st) {
        int seg = kc >> 2;
        int off = (kc & 3) * 32;
        const __half* base; int pitch;
        if (seg == 0)      { base = g_tH; pitch = H; }
        else if (seg == 1) { base = g_hH; pitch = H; }
        else if (seg == 2) { base = g_hH; pitch = H; }
        else               { base = g_rH; pitch = 32; }
        // A chunk: 64 rows x 32 half = 64B/row = 4 x 16B; 256 cp total
        {
            int r = tid >> 2, c8 = tid & 3;
            const __half* src = base + (size_t)s_row[seg * 64 + r] * pitch + off + c8 * 8;
            cpa16(&As[st][r][c8 * 8], src);
        }
        // B chunks: 128 n-rows x 32 half each (transposed W); 512 cp each
        int ku = wrowU[seg] + off;
        int kv = wrowV[seg] + off;
#pragma unroll
        for (int it = 0; it < 2; it++) {
            int pos = tid + it * 256;
            int n = pos >> 2, c8 = pos & 3;
            cpa16(&BU[st][n][c8 * 8], g_WtH + (size_t)n * WTP + ku + c8 * 8);
        }
        if (seg != 1) {
#pragma unroll
            for (int it = 0; it < 2; it++) {
                int pos = tid + it * 256;
                int n = pos >> 2, c8 = pos & 3;
                cpa16(&BV[st][n][c8 * 8], g_WtH + (size_t)n * WTP + kv + c8 * 8);
            }
        }
    };

    float C[2][8][4] = {};
    const int TOT = 13;

    copy_chunk(0, 0);
    CP_COMMIT();
    for (int kc = 0; kc < TOT; kc++) {
        if (kc + 1 < TOT) { copy_chunk(kc + 1, (kc + 1) & 1); CP_COMMIT(); CP_WAIT1(); }
        else              { CP_WAIT0(); }
        __syncthreads();
        int st = kc & 1;
        int seg = kc >> 2;
        if (group == 0 || seg != 1) {
            __half(*Bt)[40] = group ? BV[st] : BU[st];
            int c2 = (lane & 3) * 2;
#pragma unroll
            for (int ks2 = 0; ks2 < 2; ks2++) {
                int kb = ks2 * 16;
                unsigned a[2][4];
#pragma unroll
                for (int mt = 0; mt < 2; mt++) {
                    int rb = warp_m * 32 + mt * 16 + (lane >> 2);
                    a[mt][0] = *(const unsigned*)&As[st][rb][kb + c2];
                    a[mt][1] = *(const unsigned*)&As[st][rb + 8][kb + c2];
                    a[mt][2] = *(const unsigned*)&As[st][rb][kb + c2 + 8];
                    a[mt][3] = *(const unsigned*)&As[st][rb + 8][kb + c2 + 8];
                }
#pragma unroll
                for (int nt = 0; nt < 8; nt++) {
                    int nb = warp_n * 64 + nt * 8 + (lane >> 2);
                    unsigned b0 = *(const unsigned*)&Bt[nb][kb + c2];
                    unsigned b1 = *(const unsigned*)&Bt[nb][kb + c2 + 8];
                    mma_f16(C[0][nt], a[0], b0, b1);
                    mma_f16(C[1][nt], a[1], b0, b1);
                }
            }
        }
        __syncthreads();
    }

    float* outp = group ? outV : outU;
#pragma unroll
    for (int mt = 0; mt < 2; mt++) {
        int r0 = m0 + warp_m * 32 + mt * 16 + (lane >> 2);
#pragma unroll
        for (int nt = 0; nt < 8; nt++) {
            int cb = warp_n * 64 + nt * 8 + 2 * (lane & 3);
            if (r0 < E1)
                *(float2*)&outp[(size_t)r0 * H + cb] =
                    make_float2(C[mt][nt][0], C[mt][nt][1]);
            if (r0 + 8 < E1)
                *(float2*)&outp[(size_t)(r0 + 8) * H + cb] =
                    make_float2(C[mt][nt][2], C[mt][nt][3]);
        }
    }
}

// -------------- generic gathered GEMM (used for Z) ------------------------
struct GSpec {
    const float* base[4];
    const int*   idx[4];
    int          pitch[4];
    int          width[4];
    int          wrow[4];
    int          nseg;
};

__global__ void __launch_bounds__(NT) k_proj(GSpec g, int R, const float* __restrict__ W,
                                             float* __restrict__ out) {
    __shared__ float As[64][33];
    __shared__ float Bs[32][132];
    __shared__ int   s_row[4][64];
    int tid = threadIdx.x, lane = tid & 31, wid = tid >> 5;
    int warp_m = wid & 1, warp_n = wid >> 1;
    int m0 = blockIdx.x * 64;

    for (int s = 0; s < g.nseg; s++)
        for (int r = tid; r < 64; r += NT) {
            int row = m0 + r;
            s_row[s][r] = (row < R) ? (g.idx[s] ? g.idx[s][row] : row) : 0;
        }
    __syncthreads();

    float C[2][4][4] = {};
    int tot = 0;
    for (int s = 0; s < g.nseg; s++) tot += g.width[s] >> 5;

    int seg = 0, segch = 0;
    for (int kc = 0; kc < tot; kc++) {
        int off = segch * 32;
        const float* base = g.base[seg];
        int pitch = g.pitch[seg];
        const float* Wc = W + (size_t)(g.wrow[seg] + off) * H;
#pragma unroll
        for (int it = 0; it < 8; it++) {
            int pos = tid + it * NT;
            int r = pos >> 5, c = pos & 31;
            As[r][c] = to_tf32(base[(size_t)s_row[seg][r] * pitch + off + c]);
        }
#pragma unroll
        for (int it = 0; it < 16; it++) {
            int pos = tid + it * NT;
            int r = pos >> 7, c = pos & 127;
            Bs[r][c] = to_tf32(Wc[pos]);
        }
        __syncthreads();
#pragma unroll
        for (int ks = 0; ks < 4; ks++) {
            int k0 = ks * 8;
            unsigned a[2][4];
#pragma unroll
            for (int mt = 0; mt < 2; mt++) {
                int rb = warp_m * 32 + mt * 16 + (lane >> 2);
                int cb = k0 + (lane & 3);
                a[mt][0] = __float_as_uint(As[rb][cb]);
                a[mt][1] = __float_as_uint(As[rb + 8][cb]);
                a[mt][2] = __float_as_uint(As[rb][cb + 4]);
                a[mt][3] = __float_as_uint(As[rb + 8][cb + 4]);
            }
#pragma unroll
            for (int nt = 0; nt < 4; nt++) {
                int nb = warp_n * 32 + nt * 8 + (lane >> 2);
                unsigned b0 = __float_as_uint(Bs[k0 + (lane & 3)][nb]);
                unsigned b1 = __float_as_uint(Bs[k0 + (lane & 3) + 4][nb]);
                mma_tf32(C[0][nt], a[0], b0, b1);
                mma_tf32(C[1][nt], a[1], b0, b1);
            }
        }
        __syncthreads();
        segch++;
        if ((segch << 5) >= g.width[seg]) { seg++; segch = 0; }
    }

#pragma unroll
    for (int mt = 0; mt < 2; mt++) {
        int r0 = warp_m * 32 + mt * 16 + (lane >> 2);
#pragma unroll
        for (int nt = 0; nt < 4; nt++) {
            int cb = warp_n * 32 + nt * 8 + 2 * (lane & 3);
            int row = m0 + r0;
            if (row < R)
                *(float2*)&out[(size_t)row * H + cb] = make_float2(C[mt][nt][0], C[mt][nt][1]);
            if (row + 8 < R)
                *(float2*)&out[(size_t)(row + 8) * H + cb] = make_float2(C[mt][nt][2], C[mt][nt][3]);
        }
    }
}

// ---- per-e2 hidden sum: S[q] = sum_w silu(U[eik]+V[ekj]+Z[q]+c*w864+b1) ---
__global__ void __launch_bounds__(NT) k_hsum(const float* __restrict__ sph,
                                             const float* __restrict__ w1,
                                             const float* __restrict__ b1, int E2) {
    int warp = (blockIdx.x * blockDim.x + threadIdx.x) >> 5;
    int lane = threadIdx.x & 31;
    if (warp >= E2) return;
    int q = warp;
    int beg = g_wptr[q], end = g_wptr[q + 1];
    if (beg > WCAP) beg = WCAP;
    if (end > WCAP) end = WCAP;
    float4 z  = *(const float4*)&g_Z[(size_t)q * H + lane * 4];
    float4 w8 = *(const float4*)&w1[(size_t)864 * H + lane * 4];
    float4 bb = *(const float4*)&b1[lane * 4];
    float4 acc = make_float4(0.f, 0.f, 0.f, 0.f);

    float4 u, v; float cf = 0.f;
    int w = beg;
    if (w < end) {
        int a = g_weik[w], b = g_wekj[w];
        cf = __ldg(&sph[a * 3 + 1]) * __ldg(&sph[b * 3 + 1]);
        u = *(const float4*)&g_U[(size_t)a * H + lane * 4];
        v = *(const float4*)&g_V[(size_t)b * H + lane * 4];
    }
    while (w < end) {
        float4 cu = u, cv = v; float c0 = cf;
        int nw = w + 1;
        if (nw < end) {
            int a = g_weik[nw], b = g_wekj[nw];
            cf = __ldg(&sph[a * 3 + 1]) * __ldg(&sph[b * 3 + 1]);
            u = *(const float4*)&g_U[(size_t)a * H + lane * 4];
            v = *(const float4*)&g_V[(size_t)b * H + lane * 4];
        }
        float x;
        x = cu.x + cv.x + z.x + c0 * w8.x + bb.x; acc.x += x / (1.f + __expf(-x));
        x = cu.y + cv.y + z.y + c0 * w8.y + bb.y; acc.y += x / (1.f + __expf(-x));
        x = cu.z + cv.z + z.z + c0 * w8.z + bb.z; acc.z += x / (1.f + __expf(-x));
        x = cu.w + cv.w + z.w + c0 * w8.w + bb.w; acc.w += x / (1.f + __expf(-x));
        w = nw;
    }
    *(float4*)&g_S[(size_t)q * H + lane * 4] = acc;
}

// ---- final (unified 12-chunk cp.async pipeline, fp16 mma):
//  chunks 0-3:  C  = S @ W2      (A = Ss)
//  chunks 4-7:  C2 = m @ wgw     (A = Ms, written at kc==3; Ss reloaded w/ t)
//  chunks 8-11: C3 = t @ wgt     (A = Ss)
//  out = t + sigmoid(C2+bgw) * tanh(C3+bgt)
__global__ void __launch_bounds__(NT) k_final(const float* __restrict__ t_e2,
                                              const float* __restrict__ w2,
                                              const float* __restrict__ b2,
                                              const float* __restrict__ wgw,
                                              const float* __restrict__ bgw,
                                              const float* __restrict__ wgt,
                                              const float* __restrict__ bgt,
                                              int E2, float* __restrict__ out) {
    extern __shared__ float sm[];
    float(*Ss)[132] = (float(*)[132])sm;                           // 64 x 132
    float(*Ms)[132] = (float(*)[132])(sm + 64 * 132);              // 64 x 132
    float(*Bs)[32][132] = (float(*)[32][132])(sm + 2 * 64 * 132);  // 2 stages
    __shared__ int s_cnt[64];

    int tid = threadIdx.x, lane = tid & 31, wid = tid >> 5;
    int warp_m = wid & 1, warp_n = wid >> 1;
    int m0 = blockIdx.x * 64;

    for (int r = tid; r < 64; r += NT) {
        int row = m0 + r;
        s_cnt[r] = (row < E2) ? (g_wptr[row + 1] - g_wptr[row]) : 0;
    }
#pragma unroll
    for (int it = 0; it < 8; it++) {
        int pos = tid + it * NT;
        int r = pos >> 5, c4 = pos & 31;
        int row = m0 + r;
        float4 v = (row < E2) ? *(const float4*)&g_S[(size_t)row * H + c4 * 4]
                              : make_float4(0.f, 0.f, 0.f, 0.f);
        *(float4*)&Ss[r][c4 * 4] = v;
    }

    auto loadB = [&](int kc, int st) {
        const float* Wc;
        if (kc < 4)      Wc = w2  + (size_t)kc * 32 * H;
        else if (kc < 8) Wc = wgw + (size_t)(kc - 4) * 32 * H;
        else             Wc = wgt + (size_t)(kc - 8) * 32 * H;
#pragma unroll
        for (int it = 0; it < 4; it++) {
            int pos = tid + it * NT;
            int r = pos >> 5, c4 = pos & 31;
            cpa16(&Bs[st][r][c4 * 4], Wc + r * H + c4 * 4);
        }
    };

    float C[2][4][4] = {};
    float C2[2][4][4] = {};
    float C3[2][4][4] = {};
    loadB(0, 0);
    CP_COMMIT();
    __syncthreads();
    for (int kc = 0; kc < 12; kc++) {
        if (kc + 1 < 12) { loadB(kc + 1, (kc + 1) & 1); CP_COMMIT(); CP_WAIT1(); }
        else             { CP_WAIT0(); }
        __syncthreads();
        int st = kc & 1;
        int stage = kc >> 2;
        int kcol = (kc & 3) * 32;
        float(*Asrc)[132] = (stage == 1) ? Ms : Ss;
        int c2 = (lane & 3) * 2;
#pragma unroll
        for (int ks2 = 0; ks2 < 2; ks2++) {
            int ka = kcol + ks2 * 16;
            int kb = ks2 * 16;
            unsigned a[2][4];
#pragma unroll
            for (int mt = 0; mt < 2; mt++) {
                int rb = warp_m * 32 + mt * 16 + (lane >> 2);
                a[mt][0] = pack2(Asrc[rb][ka + c2],         Asrc[rb][ka + c2 + 1]);
                a[mt][1] = pack2(Asrc[rb + 8][ka + c2],     Asrc[rb + 8][ka + c2 + 1]);
                a[mt][2] = pack2(Asrc[rb][ka + c2 + 8],     Asrc[rb][ka + c2 + 9]);
                a[mt][3] = pack2(Asrc[rb + 8][ka + c2 + 8], Asrc[rb + 8][ka + c2 + 9]);
            }
#pragma unroll
            for (int nt = 0; nt < 4; nt++) {
                int nb = warp_n * 32 + nt * 8 + (lane >> 2);
                unsigned b0 = pack2(Bs[st][kb + c2][nb],     Bs[st][kb + c2 + 1][nb]);
                unsigned b1 = pack2(Bs[st][kb + c2 + 8][nb], Bs[st][kb + c2 + 9][nb]);
                if (stage == 0)      { mma_f16(C[0][nt],  a[0], b0, b1); mma_f16(C[1][nt],  a[1], b0, b1); }
                else if (stage == 1) { mma_f16(C2[0][nt], a[0], b0, b1); mma_f16(C2[1][nt], a[1], b0, b1); }
                else                 { mma_f16(C3[0][nt], a[0], b0, b1); mma_f16(C3[1][nt], a[1], b0, b1); }
            }
        }
        __syncthreads();
        if (kc == 3) {
#pragma unroll
            for (int mt = 0; mt < 2; mt++) {
                int r0 = warp_m * 32 + mt * 16 + (lane >> 2);
                float cn0 = (float)s_cnt[r0], cn1 = (float)s_cnt[r0 + 8];
#pragma unroll
                for (int nt = 0; nt < 4; nt++) {
                    int cb = warp_n * 32 + nt * 8 + 2 * (lane & 3);
                    Ms[r0][cb]         = C[mt][nt][0] + cn0 * b2[cb];
                    Ms[r0][cb + 1]     = C[mt][nt][1] + cn0 * b2[cb + 1];
                    Ms[r0 + 8][cb]     = C[mt][nt][2] + cn1 * b2[cb];
                    Ms[r0 + 8][cb + 1] = C[mt][nt][3] + cn1 * b2[cb + 1];
                }
            }
#pragma unroll
            for (int it = 0; it < 8; it++) {
                int pos = tid + it * NT;
                int r = pos >> 5, c4 = pos & 31;
                int row = m0 + r;
                float4 v = (row < E2) ? *(const float4*)&t_e2[(size_t)row * H + c4 * 4]
                                      : make_float4(0.f, 0.f, 0.f, 0.f);
                *(float4*)&Ss[r][c4 * 4] = v;
            }
            __syncthreads();
        }
    }

#pragma unroll
    for (int mt = 0; mt < 2; mt++) {
        int rl = warp_m * 32 + mt * 16 + (lane >> 2);
#pragma unroll
        for (int nt = 0; nt < 4; nt++) {
            int cb = warp_n * 32 + nt * 8 + 2 * (lane & 3);
#pragma unroll
            for (int half = 0; half < 2; half++) {
                int row = m0 + rl + half * 8;
                if (row >= E2) continue;
#pragma unroll
                for (int e = 0; e < 2; e++) {
                    int col = cb + e;
                    float gw = C2[mt][nt][half * 2 + e] + bgw[col];
                    float gt = C3[mt][nt][half * 2 + e] + bgt[col];
                    float sig = 1.f / (1.f + __expf(-gw));
                    out[(size_t)row * H + col] =
                        Ss[rl + half * 8][col] + sig * tanhf(gt);
                }
            }
        }
    }
}

// --------------------------------------------------------------------------
extern "C" void kernel_launch(void* const* d_in, const int* in_sizes, int n_in,
                              void* d_out, int out_size) {
    const float* t_e2 = (const float*)d_in[0];
    const float* h    = (const float*)d_in[1];
    const int*   ei1  = (const int*)d_in[2];
    const int*   ei2  = (const int*)d_in[3];
    const int*   e1e2 = (const int*)d_in[4];
    const float* rbf1 = (const float*)d_in[7];
    const float* rbf2 = (const float*)d_in[8];
    const float* sph  = (const float*)d_in[9];
    const int*   nn_p = (const int*)d_in[10];
    const float* w1   = (const float*)d_in[11];
    const float* b1   = (const float*)d_in[12];
    const float* w2   = (const float*)d_in[13];
    const float* b2   = (const float*)d_in[14];
    const float* wgw  = (const float*)d_in[15];
    const float* bgw  = (const float*)d_in[16];
    const float* wgt  = (const float*)d_in[17];
    const float* bgt  = (const float*)d_in[18];

    int E1 = in_sizes[4];
    int E2 = in_sizes[0] / H;
    int NN = in_sizes[1] / H;
    const int* src1 = ei1;
    const int* dst1 = ei1 + E1;
    const int* src2 = ei2;
    const int* dst2 = ei2 + E2;

    float *pU, *pV, *pZ;
    __half *ptH, *phH, *prH;
    cudaGetSymbolAddress((void**)&pU, g_U);
    cudaGetSymbolAddress((void**)&pV, g_V);
    cudaGetSymbolAddress((void**)&pZ, g_Z);
    cudaGetSymbolAddress((void**)&ptH, g_tH);
    cudaGetSymbolAddress((void**)&phH, g_hH);
    cudaGetSymbolAddress((void**)&prH, g_rH);

    size_t fsmem = (size_t)(2 * 64 * 132 + 2 * 32 * 132) * 4;
    cudaFuncSetAttribute(k_final, cudaFuncAttributeMaxDynamicSharedMemorySize, (int)fsmem);
    size_t uvsmem = (size_t)(2 * 64 * 40 + 4 * 128 * 40) * 2 + 4 * 64 * sizeof(int);
    cudaFuncSetAttribute(k_projUV, cudaFuncAttributeMaxDynamicSharedMemorySize, (int)uvsmem);

    static cudaStream_t s1 = nullptr, s2 = nullptr;
    static cudaEvent_t evRoot = nullptr, ev1 = nullptr, ev2 = nullptr;
    if (!s1) {
        cudaStreamCreateWithFlags(&s1, cudaStreamNonBlocking);
        cudaStreamCreateWithFlags(&s2, cudaStreamNonBlocking);
        cudaEventCreateWithFlags(&evRoot, cudaEventDisableTiming);
        cudaEventCreateWithFlags(&ev1, cudaEventDisableTiming);
        cudaEventCreateWithFlags(&ev2, cudaEventDisableTiming);
    }

    // ---- fork ----
    cudaEventRecord(evRoot, 0);
    cudaStreamWaitEvent(s1, evRoot, 0);
    cudaStreamWaitEvent(s2, evRoot, 0);

    // s1: fp16 pre-conversion (same stream => ordered before projUV)
    {
        int n2;
        n2 = E2 * H / 2;  k_cvtA<<<(n2 + NT - 1) / NT, NT, 0, s1>>>(t_e2, ptH, n2);
        n2 = NN * H / 2;  k_cvtA<<<(n2 + NT - 1) / NT, NT, 0, s1>>>(h, phH, n2);
        n2 = E1 * 32 / 2; k_cvtA<<<(n2 + NT - 1) / NT, NT, 0, s1>>>(rbf1, prH, n2);
        int nw = 865 * H; k_cvtW<<<(nw + NT - 1) / NT, NT, 0, s1>>>(w1);
    }
    // s1: merged U+V projection (pure fp16 tiles)
    k_projUV<<<(E1 + 63) / 64, 256, uvsmem, s1>>>(e1e2, src1, dst1, E1, pU, pV);
    cudaEventRecord(ev1, s1);

    // s2: Z projection
    {
        GSpec gz;
        gz.nseg = 2;
        gz.base[0] = t_e2; gz.idx[0] = nullptr; gz.pitch[0] = H;  gz.width[0] = 128; gz.wrow[0] = 256;
        gz.base[1] = rbf2; gz.idx[1] = nullptr; gz.pitch[1] = 32; gz.width[1] = 32;  gz.wrow[1] = 832;
        gz.base[2] = t_e2; gz.idx[2] = nullptr; gz.pitch[2] = H;  gz.width[2] = 0;   gz.wrow[2] = 0;
        gz.base[3] = t_e2; gz.idx[3] = nullptr; gz.pitch[3] = H;  gz.width[3] = 0;   gz.wrow[3] = 0;
        k_proj<<<(E2 + 63) / 64, NT, 0, s2>>>(gz, E2, w1, pZ);
    }
    cudaEventRecord(ev2, s2);

    // default stream: wedge-list construction chain
    k_ptr<<<(NMAX + 1 + NT - 1) / NT, NT>>>(src1, E1, nn_p);
    k_count<<<(E2 + NT - 1) / NT, NT>>>(src2, dst2, dst1, E2);
    int nscan = (E2 + 2047) / 2048;
    k_scan_part<<<nscan, NT>>>(E2);
    k_scan_top<<<1, 32>>>(nscan, E2);
    k_scan_write<<<nscan, NT>>>(E2);
    k_fill<<<(E2 + NT - 1) / NT, NT>>>(src2, dst2, dst1, E2);

    // ---- join ----
    cudaStreamWaitEvent(0, ev1, 0);
    cudaStreamWaitEvent(0, ev2, 0);

    // per-e2 hidden sum
    {
        int blocks = (E2 * 32 + NT - 1) / NT;
        k_hsum<<<blocks, NT>>>(sph, w1, b1, E2);
    }

    // final: unified pipelined 3-stage GEMM (fp16 mma) + gated output
    k_final<<<(E2 + 63) / 64, NT, fsmem>>>(t_e2, w2, b2, wgw, bgw, wgt, bgt, E2,
                                           (float*)d_out);
}

// round 16
// speedup vs baseline: 1.2198x; 1.0111x over previous
#include <cuda_runtime.h>
#include <cuda_fp16.h>

#define H     128
#define NT    256
#define NMAX  10016
#define E1MAX 80000
#define E2MAX 80000
#define WCAP  (E1MAX*16)
#define WTP   872   // padded k-pitch of transposed half W1

// ------- scratch (static device globals; no runtime allocation) ----------
__device__ int    g_ptr[NMAX + 2];
__device__ int    g_cnt[E2MAX];
__device__ int    g_part[128];
__device__ int    g_wptr[E2MAX + 1];
__device__ int    g_weik[WCAP];
__device__ int    g_wekj[WCAP];
__device__ __half g_UH[(size_t)E1MAX * H];
__device__ __half g_VH[(size_t)E1MAX * H];
__device__ float  g_Z[(size_t)E2MAX * H];
__device__ float  g_S[(size_t)E2MAX * H];
__device__ __half g_tH[(size_t)E2MAX * H];
__device__ __half g_hH[(size_t)NMAX * H];
__device__ __half g_rH[(size_t)E1MAX * 32];
__device__ __half g_WtH[(size_t)H * WTP];

// ------------------------- helpers ---------------------------------------
__device__ __forceinline__ float to_tf32(float x) {
    unsigned u;
    asm("cvt.rna.tf32.f32 %0, %1;" : "=r"(u) : "f"(x));
    return __uint_as_float(u);
}

__device__ __forceinline__ void mma_tf32(float c[4], const unsigned a[4],
                                         unsigned b0, unsigned b1) {
    asm volatile(
        "mma.sync.aligned.m16n8k8.row.col.f32.tf32.tf32.f32 "
        "{%0,%1,%2,%3}, {%4,%5,%6,%7}, {%8,%9}, {%0,%1,%2,%3};"
        : "+f"(c[0]), "+f"(c[1]), "+f"(c[2]), "+f"(c[3])
        : "r"(a[0]), "r"(a[1]), "r"(a[2]), "r"(a[3]), "r"(b0), "r"(b1));
}

__device__ __forceinline__ void mma_f16(float c[4], const unsigned a[4],
                                        unsigned b0, unsigned b1) {
    asm volatile(
        "mma.sync.aligned.m16n8k16.row.col.f32.f16.f16.f32 "
        "{%0,%1,%2,%3}, {%4,%5,%6,%7}, {%8,%9}, {%0,%1,%2,%3};"
        : "+f"(c[0]), "+f"(c[1]), "+f"(c[2]), "+f"(c[3])
        : "r"(a[0]), "r"(a[1]), "r"(a[2]), "r"(a[3]), "r"(b0), "r"(b1));
}

__device__ __forceinline__ unsigned pack2(float lo, float hi) {
    __half2 h = __floats2half2_rn(lo, hi);
    return *reinterpret_cast<unsigned*>(&h);
}

__device__ __forceinline__ void cpa16(void* sdst, const void* gsrc) {
    unsigned s = (unsigned)__cvta_generic_to_shared(sdst);
    asm volatile("cp.async.cg.shared.global [%0], [%1], 16;\n" :: "r"(s), "l"(gsrc));
}
#define CP_COMMIT() asm volatile("cp.async.commit_group;\n")
#define CP_WAIT0()  asm volatile("cp.async.wait_group 0;\n")
#define CP_WAIT1()  asm volatile("cp.async.wait_group 1;\n")

// ---------------- fp16 pre-conversion kernels -----------------------------
__global__ void k_cvtA(const float* __restrict__ src, __half* __restrict__ dst, int n2) {
    int i = blockIdx.x * blockDim.x + threadIdx.x;
    if (i < n2) {
        float2 v = ((const float2*)src)[i];
        ((__half2*)dst)[i] = __floats2half2_rn(v.x, v.y);
    }
}
__global__ void k_cvtW(const float* __restrict__ W) {
    int idx = blockIdx.x * blockDim.x + threadIdx.x;
    if (idx < 865 * H) {
        int k = idx >> 7, n = idx & 127;
        g_WtH[(size_t)n * WTP + k] = __float2half(W[idx]);
    }
}

// ---------------- CSR ptr: g_ptr[v] = lower_bound(src1, v) ---------------
__global__ void k_ptr(const int* __restrict__ src1, int E1, const int* __restrict__ nn_p) {
    int v = blockIdx.x * blockDim.x + threadIdx.x;
    int nn = *nn_p;
    if (v > nn || v > NMAX) return;
    int lo = 0, hi = E1;
    while (lo < hi) { int mid = (lo + hi) >> 1; if (src1[mid] < v) lo = mid + 1; else hi = mid; }
    g_ptr[v] = lo;
}

// ------------- per-e2-edge wedge count (sorted-by-eij build) --------------
__global__ void k_count(const int* __restrict__ src2, const int* __restrict__ dst2,
                        const int* __restrict__ dst1, int E2) {
    int q = blockIdx.x * blockDim.x + threadIdx.x;
    if (q >= E2) return;
    int i = src2[q], j = dst2[q];
    int c = 0;
    if (i != j) {
        int b0 = g_ptr[i], e0 = g_ptr[i + 1];
        for (int t = b0; t < e0; t++) {
            int k = dst1[t];
            if (k == i || k == j) continue;
            int b1 = g_ptr[k], e1 = g_ptr[k + 1];
            for (int u = b1; u < e1; u++)
                if (dst1[u] == j) c++;
        }
    }
    g_cnt[q] = c;
}

// ----------------------- 3-phase exclusive scan ---------------------------
__global__ void k_scan_part(int n) {
    int blk = blockIdx.x, tid = threadIdx.x, lane = tid & 31, wid = tid >> 5;
    int base = blk * 2048 + tid * 8;
    int s = 0;
#pragma unroll
    for (int i = 0; i < 8; i++) { int idx = base + i; if (idx < n) s += g_cnt[idx]; }
#pragma unroll
    for (int off = 16; off > 0; off >>= 1) s += __shfl_down_sync(0xffffffffu, s, off);
    __shared__ int red[8];
    if (lane == 0) red[wid] = s;
    __syncthreads();
    if (tid == 0) {
        int tot = 0;
#pragma unroll
        for (int w = 0; w < 8; w++) tot += red[w];
        g_part[blk] = tot;
    }
}
__global__ void k_scan_top(int nb, int n) {
    if (threadIdx.x == 0) {
        int acc = 0;
        for (int b = 0; b < nb; b++) { int v = g_part[b]; g_part[b] = acc; acc += v; }
        g_wptr[n] = acc;
    }
}
__global__ void k_scan_write(int n) {
    int blk = blockIdx.x, tid = threadIdx.x, lane = tid & 31, wid = tid >> 5;
    int base = blk * 2048 + tid * 8;
    int v[8]; int s = 0;
#pragma unroll
    for (int i = 0; i < 8; i++) {
        int idx = base + i;
        v[i] = (idx < n) ? g_cnt[idx] : 0;
        s += v[i];
    }
    int x = s;
#pragma unroll
    for (int off = 1; off < 32; off <<= 1) {
        int t = __shfl_up_sync(0xffffffffu, x, off);
        if (lane >= off) x += t;
    }
    __shared__ int wsum[8];
    if (lane == 31) wsum[wid] = x;
    __syncthreads();
    __shared__ int wexc[8];
    if (tid == 0) {
        int acc = 0;
#pragma unroll
        for (int w = 0; w < 8; w++) { wexc[w] = acc; acc += wsum[w]; }
    }
    __syncthreads();
    int run = g_part[blk] + wexc[wid] + x - s;
#pragma unroll
    for (int i = 0; i < 8; i++) {
        int idx = base + i;
        if (idx < n) g_wptr[idx] = run;
        run += v[i];
    }
}

__global__ void k_fill(const int* __restrict__ src2, const int* __restrict__ dst2,
                       const int* __restrict__ dst1, int E2) {
    int q = blockIdx.x * blockDim.x + threadIdx.x;
    if (q >= E2) return;
    int i = src2[q], j = dst2[q];
    if (i == j) return;
    int pos = g_wptr[q];
    int b0 = g_ptr[i], e0 = g_ptr[i + 1];
    for (int t = b0; t < e0; t++) {
        int k = dst1[t];
        if (k == i || k == j) continue;
        int b1 = g_ptr[k], e1 = g_ptr[k + 1];
        for (int u = b1; u < e1; u++)
            if (dst1[u] == j) {
                if (pos < WCAP) { g_weik[pos] = t; g_wekj[pos] = u; }
                pos++;
            }
    }
}

// ---------- merged U+V projection: pure-fp16 smem, half output ------------
__global__ void __launch_bounds__(256, 2) k_projUV(
    const int* __restrict__ e1e2, const int* __restrict__ src1,
    const int* __restrict__ dst1,
    int E1, __half* __restrict__ outU, __half* __restrict__ outV) {
    extern __shared__ __half smh[];
    __half(*As)[64][40]  = (__half(*)[64][40])smh;                    // 2 stages
    __half(*BU)[128][40] = (__half(*)[128][40])(smh + 2 * 64 * 40);
    __half(*BV)[128][40] = (__half(*)[128][40])(smh + 2 * 64 * 40 + 2 * 128 * 40);
    int* s_row = (int*)(smh + 2 * 64 * 40 + 4 * 128 * 40);            // [4][64]

    int tid = threadIdx.x, lane = tid & 31, wid = tid >> 5;
    int group = wid >> 2;            // 0 = U, 1 = V
    int warp_m = wid & 1;            // 2 row groups of 32
    int warp_n = (wid >> 1) & 1;     // 2 col groups of 64
    int m0 = blockIdx.x * 64;

    for (int r = tid; r < 64; r += 256) {
        int row = m0 + r;
        int rc = (row < E1) ? row : 0;
        s_row[0 * 64 + r] = (row < E1) ? e1e2[row] : 0;
        s_row[1 * 64 + r] = (row < E1) ? src1[row] : 0;
        s_row[2 * 64 + r] = (row < E1) ? dst1[row] : 0;
        s_row[3 * 64 + r] = rc;
    }
    __syncthreads();

    const int wrowU[4] = {0, 384, 512, 768};
    const int wrowV[4] = {128, 0, 640, 800};

    auto copy_chunk = [&](int kc, int st) {
        int seg = kc >> 2;
        int off = (kc & 3) * 32;
        const __half* base; int pitch;
        if (seg == 0)      { base = g_tH; pitch = H; }
        else if (seg == 1) { base = g_hH; pitch = H; }
        else if (seg == 2) { base = g_hH; pitch = H; }
        else               { base = g_rH; pitch = 32; }
        {
            int r = tid >> 2, c8 = tid & 3;
            const __half* src = base + (size_t)s_row[seg * 64 + r] * pitch + off + c8 * 8;
            cpa16(&As[st][r][c8 * 8], src);
        }
        int ku = wrowU[seg] + off;
        int kv = wrowV[seg] + off;
#pragma unroll
        for (int it = 0; it < 2; it++) {
            int pos = tid + it * 256;
            int n = pos >> 2, c8 = pos & 3;
            cpa16(&BU[st][n][c8 * 8], g_WtH + (size_t)n * WTP + ku + c8 * 8);
        }
        if (seg != 1) {
#pragma unroll
            for (int it = 0; it < 2; it++) {
                int pos = tid + it * 256;
                int n = pos >> 2, c8 = pos & 3;
                cpa16(&BV[st][n][c8 * 8], g_WtH + (size_t)n * WTP + kv + c8 * 8);
            }
        }
    };

    float C[2][8][4] = {};
    const int TOT = 13;

    copy_chunk(0, 0);
    CP_COMMIT();
    for (int kc = 0; kc < TOT; kc++) {
        if (kc + 1 < TOT) { copy_chunk(kc + 1, (kc + 1) & 1); CP_COMMIT(); CP_WAIT1(); }
        else              { CP_WAIT0(); }
        __syncthreads();
        int st = kc & 1;
        int seg = kc >> 2;
        if (group == 0 || seg != 1) {
            __half(*Bt)[40] = group ? BV[st] : BU[st];
            int c2 = (lane & 3) * 2;
#pragma unroll
            for (int ks2 = 0; ks2 < 2; ks2++) {
                int kb = ks2 * 16;
                unsigned a[2][4];
#pragma unroll
                for (int mt = 0; mt < 2; mt++) {
                    int rb = warp_m * 32 + mt * 16 + (lane >> 2);
                    a[mt][0] = *(const unsigned*)&As[st][rb][kb + c2];
                    a[mt][1] = *(const unsigned*)&As[st][rb + 8][kb + c2];
                    a[mt][2] = *(const unsigned*)&As[st][rb][kb + c2 + 8];
                    a[mt][3] = *(const unsigned*)&As[st][rb + 8][kb + c2 + 8];
                }
#pragma unroll
                for (int nt = 0; nt < 8; nt++) {
                    int nb = warp_n * 64 + nt * 8 + (lane >> 2);
                    unsigned b0 = *(const unsigned*)&Bt[nb][kb + c2];
                    unsigned b1 = *(const unsigned*)&Bt[nb][kb + c2 + 8];
                    mma_f16(C[0][nt], a[0], b0, b1);
                    mma_f16(C[1][nt], a[1], b0, b1);
                }
            }
        }
        __syncthreads();
    }

    // epilogue: store as half (pack2) — halves store traffic; only hsum reads
    __half* outp = group ? outV : outU;
#pragma unroll
    for (int mt = 0; mt < 2; mt++) {
        int r0 = m0 + warp_m * 32 + mt * 16 + (lane >> 2);
#pragma unroll
        for (int nt = 0; nt < 8; nt++) {
            int cb = warp_n * 64 + nt * 8 + 2 * (lane & 3);
            if (r0 < E1)
                *(unsigned*)&outp[(size_t)r0 * H + cb] = pack2(C[mt][nt][0], C[mt][nt][1]);
            if (r0 + 8 < E1)
                *(unsigned*)&outp[(size_t)(r0 + 8) * H + cb] = pack2(C[mt][nt][2], C[mt][nt][3]);
        }
    }
}

// -------------- generic gathered GEMM (used for Z) ------------------------
struct GSpec {
    const float* base[4];
    const int*   idx[4];
    int          pitch[4];
    int          width[4];
    int          wrow[4];
    int          nseg;
};

__global__ void __launch_bounds__(NT) k_proj(GSpec g, int R, const float* __restrict__ W,
                                             float* __restrict__ out) {
    __shared__ float As[64][33];
    __shared__ float Bs[32][132];
    __shared__ int   s_row[4][64];
    int tid = threadIdx.x, lane = tid & 31, wid = tid >> 5;
    int warp_m = wid & 1, warp_n = wid >> 1;
    int m0 = blockIdx.x * 64;

    for (int s = 0; s < g.nseg; s++)
        for (int r = tid; r < 64; r += NT) {
            int row = m0 + r;
            s_row[s][r] = (row < R) ? (g.idx[s] ? g.idx[s][row] : row) : 0;
        }
    __syncthreads();

    float C[2][4][4] = {};
    int tot = 0;
    for (int s = 0; s < g.nseg; s++) tot += g.width[s] >> 5;

    int seg = 0, segch = 0;
    for (int kc = 0; kc < tot; kc++) {
        int off = segch * 32;
        const float* base = g.base[seg];
        int pitch = g.pitch[seg];
        const float* Wc = W + (size_t)(g.wrow[seg] + off) * H;
#pragma unroll
        for (int it = 0; it < 8; it++) {
            int pos = tid + it * NT;
            int r = pos >> 5, c = pos & 31;
            As[r][c] = to_tf32(base[(size_t)s_row[seg][r] * pitch + off + c]);
        }
#pragma unroll
        for (int it = 0; it < 16; it++) {
            int pos = tid + it * NT;
            int r = pos >> 7, c = pos & 127;
            Bs[r][c] = to_tf32(Wc[pos]);
        }
        __syncthreads();
#pragma unroll
        for (int ks = 0; ks < 4; ks++) {
            int k0 = ks * 8;
            unsigned a[2][4];
#pragma unroll
            for (int mt = 0; mt < 2; mt++) {
                int rb = warp_m * 32 + mt * 16 + (lane >> 2);
                int cb = k0 + (lane & 3);
                a[mt][0] = __float_as_uint(As[rb][cb]);
                a[mt][1] = __float_as_uint(As[rb + 8][cb]);
                a[mt][2] = __float_as_uint(As[rb][cb + 4]);
                a[mt][3] = __float_as_uint(As[rb + 8][cb + 4]);
            }
#pragma unroll
            for (int nt = 0; nt < 4; nt++) {
                int nb = warp_n * 32 + nt * 8 + (lane >> 2);
                unsigned b0 = __float_as_uint(Bs[k0 + (lane & 3)][nb]);
                unsigned b1 = __float_as_uint(Bs[k0 + (lane & 3) + 4][nb]);
                mma_tf32(C[0][nt], a[0], b0, b1);
                mma_tf32(C[1][nt], a[1], b0, b1);
            }
        }
        __syncthreads();
        segch++;
        if ((segch << 5) >= g.width[seg]) { seg++; segch = 0; }
    }

#pragma unroll
    for (int mt = 0; mt < 2; mt++) {
        int r0 = warp_m * 32 + mt * 16 + (lane >> 2);
#pragma unroll
        for (int nt = 0; nt < 4; nt++) {
            int cb = warp_n * 32 + nt * 8 + 2 * (lane & 3);
            int row = m0 + r0;
            if (row < R)
                *(float2*)&out[(size_t)row * H + cb] = make_float2(C[mt][nt][0], C[mt][nt][1]);
            if (row + 8 < R)
                *(float2*)&out[(size_t)(row + 8) * H + cb] = make_float2(C[mt][nt][2], C[mt][nt][3]);
        }
    }
}

// ---- per-e2 hidden sum (half U/V gather): S[q] = sum_w silu(...) ---------
__global__ void __launch_bounds__(NT) k_hsum(const float* __restrict__ sph,
                                             const float* __restrict__ w1,
                                             const float* __restrict__ b1, int E2) {
    int warp = (blockIdx.x * blockDim.x + threadIdx.x) >> 5;
    int lane = threadIdx.x & 31;
    if (warp >= E2) return;
    int q = warp;
    int beg = g_wptr[q], end = g_wptr[q + 1];
    if (beg > WCAP) beg = WCAP;
    if (end > WCAP) end = WCAP;
    float4 z  = *(const float4*)&g_Z[(size_t)q * H + lane * 4];
    float4 w8 = *(const float4*)&w1[(size_t)864 * H + lane * 4];
    float4 bb = *(const float4*)&b1[lane * 4];
    float4 acc = make_float4(0.f, 0.f, 0.f, 0.f);

    uint2 u, v; float cf = 0.f;
    int w = beg;
    if (w < end) {
        int a = g_weik[w], b = g_wekj[w];
        cf = __ldg(&sph[a * 3 + 1]) * __ldg(&sph[b * 3 + 1]);
        u = *(const uint2*)&g_UH[(size_t)a * H + lane * 4];
        v = *(const uint2*)&g_VH[(size_t)b * H + lane * 4];
    }
    while (w < end) {
        uint2 cu = u, cv = v; float c0 = cf;
        int nw = w + 1;
        if (nw < end) {
            int a = g_weik[nw], b = g_wekj[nw];
            cf = __ldg(&sph[a * 3 + 1]) * __ldg(&sph[b * 3 + 1]);
            u = *(const uint2*)&g_UH[(size_t)a * H + lane * 4];
            v = *(const uint2*)&g_VH[(size_t)b * H + lane * 4];
        }
        float2 u01 = __half22float2(*(const __half2*)&cu.x);
        float2 u23 = __half22float2(*(const __half2*)&cu.y);
        float2 v01 = __half22float2(*(const __half2*)&cv.x);
        float2 v23 = __half22float2(*(const __half2*)&cv.y);
        float x;
        x = u01.x + v01.x + z.x + c0 * w8.x + bb.x; acc.x += x / (1.f + __expf(-x));
        x = u01.y + v01.y + z.y + c0 * w8.y + bb.y; acc.y += x / (1.f + __expf(-x));
        x = u23.x + v23.x + z.z + c0 * w8.z + bb.z; acc.z += x / (1.f + __expf(-x));
        x = u23.y + v23.y + z.w + c0 * w8.w + bb.w; acc.w += x / (1.f + __expf(-x));
        w = nw;
    }
    *(float4*)&g_S[(size_t)q * H + lane * 4] = acc;
}

// ---- final (unified 12-chunk cp.async pipeline, fp16 mma) ----------------
__global__ void __launch_bounds__(NT) k_final(const float* __restrict__ t_e2,
                                              const float* __restrict__ w2,
                                              const float* __restrict__ b2,
                                              const float* __restrict__ wgw,
                                              const float* __restrict__ bgw,
                                              const float* __restrict__ wgt,
                                              const float* __restrict__ bgt,
                                              int E2, float* __restrict__ out) {
    extern __shared__ float sm[];
    float(*Ss)[132] = (float(*)[132])sm;                           // 64 x 132
    float(*Ms)[132] = (float(*)[132])(sm + 64 * 132);              // 64 x 132
    float(*Bs)[32][132] = (float(*)[32][132])(sm + 2 * 64 * 132);  // 2 stages
    __shared__ int s_cnt[64];

    int tid = threadIdx.x, lane = tid & 31, wid = tid >> 5;
    int warp_m = wid & 1, warp_n = wid >> 1;
    int m0 = blockIdx.x * 64;

    for (int r = tid; r < 64; r += NT) {
        int row = m0 + r;
        s_cnt[r] = (row < E2) ? (g_wptr[row + 1] - g_wptr[row]) : 0;
    }
#pragma unroll
    for (int it = 0; it < 8; it++) {
        int pos = tid + it * NT;
        int r = pos >> 5, c4 = pos & 31;
        int row = m0 + r;
        float4 v = (row < E2) ? *(const float4*)&g_S[(size_t)row * H + c4 * 4]
                              : make_float4(0.f, 0.f, 0.f, 0.f);
        *(float4*)&Ss[r][c4 * 4] = v;
    }

    auto loadB = [&](int kc, int st) {
        const float* Wc;
        if (kc < 4)      Wc = w2  + (size_t)kc * 32 * H;
        else if (kc < 8) Wc = wgw + (size_t)(kc - 4) * 32 * H;
        else             Wc = wgt + (size_t)(kc - 8) * 32 * H;
#pragma unroll
        for (int it = 0; it < 4; it++) {
            int pos = tid + it * NT;
            int r = pos >> 5, c4 = pos & 31;
            cpa16(&Bs[st][r][c4 * 4], Wc + r * H + c4 * 4);
        }
    };

    float C[2][4][4] = {};
    float C2[2][4][4] = {};
    float C3[2][4][4] = {};
    loadB(0, 0);
    CP_COMMIT();
    __syncthreads();
    for (int kc = 0; kc < 12; kc++) {
        if (kc + 1 < 12) { loadB(kc + 1, (kc + 1) & 1); CP_COMMIT(); CP_WAIT1(); }
        else             { CP_WAIT0(); }
        __syncthreads();
        int st = kc & 1;
        int stage = kc >> 2;
        int kcol = (kc & 3) * 32;
        float(*Asrc)[132] = (stage == 1) ? Ms : Ss;
        int c2 = (lane & 3) * 2;
#pragma unroll
        for (int ks2 = 0; ks2 < 2; ks2++) {
            int ka = kcol + ks2 * 16;
            int kb = ks2 * 16;
            unsigned a[2][4];
#pragma unroll
            for (int mt = 0; mt < 2; mt++) {
                int rb = warp_m * 32 + mt * 16 + (lane >> 2);
                a[mt][0] = pack2(Asrc[rb][ka + c2],         Asrc[rb][ka + c2 + 1]);
                a[mt][1] = pack2(Asrc[rb + 8][ka + c2],     Asrc[rb + 8][ka + c2 + 1]);
                a[mt][2] = pack2(Asrc[rb][ka + c2 + 8],     Asrc[rb][ka + c2 + 9]);
                a[mt][3] = pack2(Asrc[rb + 8][ka + c2 + 8], Asrc[rb + 8][ka + c2 + 9]);
            }
#pragma unroll
            for (int nt = 0; nt < 4; nt++) {
                int nb = warp_n * 32 + nt * 8 + (lane >> 2);
                unsigned b0 = pack2(Bs[st][kb + c2][nb],     Bs[st][kb + c2 + 1][nb]);
                unsigned b1 = pack2(Bs[st][kb + c2 + 8][nb], Bs[st][kb + c2 + 9][nb]);
                if (stage == 0)      { mma_f16(C[0][nt],  a[0], b0, b1); mma_f16(C[1][nt],  a[1], b0, b1); }
                else if (stage == 1) { mma_f16(C2[0][nt], a[0], b0, b1); mma_f16(C2[1][nt], a[1], b0, b1); }
                else                 { mma_f16(C3[0][nt], a[0], b0, b1); mma_f16(C3[1][nt], a[1], b0, b1); }
            }
        }
        __syncthreads();
        if (kc == 3) {
#pragma unroll
            for (int mt = 0; mt < 2; mt++) {
                int r0 = warp_m * 32 + mt * 16 + (lane >> 2);
                float cn0 = (float)s_cnt[r0], cn1 = (float)s_cnt[r0 + 8];
#pragma unroll
                for (int nt = 0; nt < 4; nt++) {
                    int cb = warp_n * 32 + nt * 8 + 2 * (lane & 3);
                    Ms[r0][cb]         = C[mt][nt][0] + cn0 * b2[cb];
                    Ms[r0][cb + 1]     = C[mt][nt][1] + cn0 * b2[cb + 1];
                    Ms[r0 + 8][cb]     = C[mt][nt][2] + cn1 * b2[cb];
                    Ms[r0 + 8][cb + 1] = C[mt][nt][3] + cn1 * b2[cb + 1];
                }
            }
#pragma unroll
            for (int it = 0; it < 8; it++) {
                int pos = tid + it * NT;
                int r = pos >> 5, c4 = pos & 31;
                int row = m0 + r;
                float4 v = (row < E2) ? *(const float4*)&t_e2[(size_t)row * H + c4 * 4]
                                      : make_float4(0.f, 0.f, 0.f, 0.f);
                *(float4*)&Ss[r][c4 * 4] = v;
            }
            __syncthreads();
        }
    }

#pragma unroll
    for (int mt = 0; mt < 2; mt++) {
        int rl = warp_m * 32 + mt * 16 + (lane >> 2);
#pragma unroll
        for (int nt = 0; nt < 4; nt++) {
            int cb = warp_n * 32 + nt * 8 + 2 * (lane & 3);
#pragma unroll
            for (int half = 0; half < 2; half++) {
                int row = m0 + rl + half * 8;
                if (row >= E2) continue;
#pragma unroll
                for (int e = 0; e < 2; e++) {
                    int col = cb + e;
                    float gw = C2[mt][nt][half * 2 + e] + bgw[col];
                    float gt = C3[mt][nt][half * 2 + e] + bgt[col];
                    float sig = 1.f / (1.f + __expf(-gw));
                    out[(size_t)row * H + col] =
                        Ss[rl + half * 8][col] + sig * tanhf(gt);
                }
            }
        }
    }
}

// --------------------------------------------------------------------------
extern "C" void kernel_launch(void* const* d_in, const int* in_sizes, int n_in,
                              void* d_out, int out_size) {
    const float* t_e2 = (const float*)d_in[0];
    const float* h    = (const float*)d_in[1];
    const int*   ei1  = (const int*)d_in[2];
    const int*   ei2  = (const int*)d_in[3];
    const int*   e1e2 = (const int*)d_in[4];
    const float* rbf1 = (const float*)d_in[7];
    const float* rbf2 = (const float*)d_in[8];
    const float* sph  = (const float*)d_in[9];
    const int*   nn_p = (const int*)d_in[10];
    const float* w1   = (const float*)d_in[11];
    const float* b1   = (const float*)d_in[12];
    const float* w2   = (const float*)d_in[13];
    const float* b2   = (const float*)d_in[14];
    const float* wgw  = (const float*)d_in[15];
    const float* bgw  = (const float*)d_in[16];
    const float* wgt  = (const float*)d_in[17];
    const float* bgt  = (const float*)d_in[18];

    int E1 = in_sizes[4];
    int E2 = in_sizes[0] / H;
    int NN = in_sizes[1] / H;
    const int* src1 = ei1;
    const int* dst1 = ei1 + E1;
    const int* src2 = ei2;
    const int* dst2 = ei2 + E2;

    float *pZ;
    __half *pUH, *pVH, *ptH, *phH, *prH;
    cudaGetSymbolAddress((void**)&pUH, g_UH);
    cudaGetSymbolAddress((void**)&pVH, g_VH);
    cudaGetSymbolAddress((void**)&pZ, g_Z);
    cudaGetSymbolAddress((void**)&ptH, g_tH);
    cudaGetSymbolAddress((void**)&phH, g_hH);
    cudaGetSymbolAddress((void**)&prH, g_rH);

    size_t fsmem = (size_t)(2 * 64 * 132 + 2 * 32 * 132) * 4;
    cudaFuncSetAttribute(k_final, cudaFuncAttributeMaxDynamicSharedMemorySize, (int)fsmem);
    size_t uvsmem = (size_t)(2 * 64 * 40 + 4 * 128 * 40) * 2 + 4 * 64 * sizeof(int);
    cudaFuncSetAttribute(k_projUV, cudaFuncAttributeMaxDynamicSharedMemorySize, (int)uvsmem);

    static cudaStream_t s1 = nullptr, s2 = nullptr;
    static cudaEvent_t evRoot = nullptr, ev1 = nullptr, ev2 = nullptr;
    if (!s1) {
        cudaStreamCreateWithFlags(&s1, cudaStreamNonBlocking);
        cudaStreamCreateWithFlags(&s2, cudaStreamNonBlocking);
        cudaEventCreateWithFlags(&evRoot, cudaEventDisableTiming);
        cudaEventCreateWithFlags(&ev1, cudaEventDisableTiming);
        cudaEventCreateWithFlags(&ev2, cudaEventDisableTiming);
    }

    // ---- fork ----
    cudaEventRecord(evRoot, 0);
    cudaStreamWaitEvent(s1, evRoot, 0);
    cudaStreamWaitEvent(s2, evRoot, 0);

    // s1: fp16 pre-conversion, then merged U+V projection (pure fp16)
    {
        int n2;
        n2 = E2 * H / 2;  k_cvtA<<<(n2 + NT - 1) / NT, NT, 0, s1>>>(t_e2, ptH, n2);
        n2 = NN * H / 2;  k_cvtA<<<(n2 + NT - 1) / NT, NT, 0, s1>>>(h, phH, n2);
        n2 = E1 * 32 / 2; k_cvtA<<<(n2 + NT - 1) / NT, NT, 0, s1>>>(rbf1, prH, n2);
        int nw = 865 * H; k_cvtW<<<(nw + NT - 1) / NT, NT, 0, s1>>>(w1);
    }
    k_projUV<<<(E1 + 63) / 64, 256, uvsmem, s1>>>(e1e2, src1, dst1, E1, pUH, pVH);
    cudaEventRecord(ev1, s1);

    // s2: Z projection
    {
        GSpec gz;
        gz.nseg = 2;
        gz.base[0] = t_e2; gz.idx[0] = nullptr; gz.pitch[0] = H;  gz.width[0] = 128; gz.wrow[0] = 256;
        gz.base[1] = rbf2; gz.idx[1] = nullptr; gz.pitch[1] = 32; gz.width[1] = 32;  gz.wrow[1] = 832;
        gz.base[2] = t_e2; gz.idx[2] = nullptr; gz.pitch[2] = H;  gz.width[2] = 0;   gz.wrow[2] = 0;
        gz.base[3] = t_e2; gz.idx[3] = nullptr; gz.pitch[3] = H;  gz.width[3] = 0;   gz.wrow[3] = 0;
        k_proj<<<(E2 + 63) / 64, NT, 0, s2>>>(gz, E2, w1, pZ);
    }
    cudaEventRecord(ev2, s2);

    // default stream: wedge-list construction chain
    k_ptr<<<(NMAX + 1 + NT - 1) / NT, NT>>>(src1, E1, nn_p);
    k_count<<<(E2 + NT - 1) / NT, NT>>>(src2, dst2, dst1, E2);
    int nscan = (E2 + 2047) / 2048;
    k_scan_part<<<nscan, NT>>>(E2);
    k_scan_top<<<1, 32>>>(nscan, E2);
    k_scan_write<<<nscan, NT>>>(E2);
    k_fill<<<(E2 + NT - 1) / NT, NT>>>(src2, dst2, dst1, E2);

    // ---- join ----
    cudaStreamWaitEvent(0, ev1, 0);
    cudaStreamWaitEvent(0, ev2, 0);

    // per-e2 hidden sum (half U/V gather)
    {
        int blocks = (E2 * 32 + NT - 1) / NT;
        k_hsum<<<blocks, NT>>>(sph, w1, b1, E2);
    }

    // final: unified pipelined 3-stage GEMM (fp16 mma) + gated output
    k_final<<<(E2 + 63) / 64, NT, fsmem>>>(t_e2, w2, b2, wgw, bgw, wgt, bgt, E2,
                                           (float*)d_out);
}